// round 1
// baseline (speedup 1.0000x reference)
#include <cuda_runtime.h>
#include <cuda_bf16.h>
#include <math.h>

// Problem constants
#define B_    4
#define S_    2048
#define HID_  1536
#define H_    12
#define HKV_  2
#define D_    128
#define NGROUPS_ 6
#define NSLOTS_ 16384
#define NTOK  (B_ * S_)        // 8192
#define QKV_N (H_*D_ + 2*HKV_*D_) // 2048

// Scratch (device globals; allocation in kernel_launch is forbidden)
__device__ float g_qkv[(size_t)NTOK * QKV_N];   // 64 MB
__device__ float g_ao [(size_t)NTOK * HID_];    // 48 MB

// ---------------------------------------------------------------------------
// GEMM: C[M,N] = A[M,K] * B[N,K]^T (+ bias[n]), all row-major, K % 16 == 0,
// M,N % 128 == 0. 128x128 tile, BK=16, 256 threads, 8x8 per thread.
// ---------------------------------------------------------------------------
#define GBM 128
#define GBN 128
#define GBK 16
#define GPAD 132

__global__ __launch_bounds__(256, 2)
void gemm_nt_bias(const float* __restrict__ A, const float* __restrict__ Bm,
                  const float* __restrict__ bias, float* __restrict__ C,
                  int M, int N, int K)
{
    __shared__ float As[GBK][GPAD];
    __shared__ float Bs[GBK][GPAD];

    int tid = threadIdx.x;
    int tx = tid & 15;      // N dir
    int ty = tid >> 4;      // M dir
    int m0 = blockIdx.y * GBM;
    int n0 = blockIdx.x * GBN;

    float acc[8][8];
    #pragma unroll
    for (int i = 0; i < 8; i++)
        #pragma unroll
        for (int j = 0; j < 8; j++) acc[i][j] = 0.f;

    for (int k0 = 0; k0 < K; k0 += GBK) {
        // Load A tile 128x16, transpose into As[k][m]
        #pragma unroll
        for (int it = 0; it < 2; it++) {
            int idx = tid + it * 256;          // 0..511
            int r  = idx >> 2;                 // row 0..127
            int c4 = idx & 3;                  // float4 col 0..3
            float4 v = *(const float4*)(A + (size_t)(m0 + r) * K + k0 + c4 * 4);
            As[c4*4+0][r] = v.x; As[c4*4+1][r] = v.y;
            As[c4*4+2][r] = v.z; As[c4*4+3][r] = v.w;
        }
        #pragma unroll
        for (int it = 0; it < 2; it++) {
            int idx = tid + it * 256;
            int r  = idx >> 2;
            int c4 = idx & 3;
            float4 v = *(const float4*)(Bm + (size_t)(n0 + r) * K + k0 + c4 * 4);
            Bs[c4*4+0][r] = v.x; Bs[c4*4+1][r] = v.y;
            Bs[c4*4+2][r] = v.z; Bs[c4*4+3][r] = v.w;
        }
        __syncthreads();

        #pragma unroll
        for (int k = 0; k < GBK; k++) {
            float ra[8], rb[8];
            float4 a0 = *(const float4*)&As[k][ty*8];
            float4 a1 = *(const float4*)&As[k][ty*8+4];
            float4 b0 = *(const float4*)&Bs[k][tx*8];
            float4 b1 = *(const float4*)&Bs[k][tx*8+4];
            ra[0]=a0.x; ra[1]=a0.y; ra[2]=a0.z; ra[3]=a0.w;
            ra[4]=a1.x; ra[5]=a1.y; ra[6]=a1.z; ra[7]=a1.w;
            rb[0]=b0.x; rb[1]=b0.y; rb[2]=b0.z; rb[3]=b0.w;
            rb[4]=b1.x; rb[5]=b1.y; rb[6]=b1.z; rb[7]=b1.w;
            #pragma unroll
            for (int i = 0; i < 8; i++)
                #pragma unroll
                for (int j = 0; j < 8; j++)
                    acc[i][j] = fmaf(ra[i], rb[j], acc[i][j]);
        }
        __syncthreads();
    }

    float bv[8];
    #pragma unroll
    for (int j = 0; j < 8; j++) bv[j] = bias ? bias[n0 + tx*8 + j] : 0.f;

    #pragma unroll
    for (int i = 0; i < 8; i++) {
        int m = m0 + ty*8 + i;
        float* cp = C + (size_t)m * N + n0 + tx*8;
        float4 r0, r1;
        r0.x = acc[i][0]+bv[0]; r0.y = acc[i][1]+bv[1];
        r0.z = acc[i][2]+bv[2]; r0.w = acc[i][3]+bv[3];
        r1.x = acc[i][4]+bv[4]; r1.y = acc[i][5]+bv[5];
        r1.z = acc[i][6]+bv[6]; r1.w = acc[i][7]+bv[7];
        *(float4*)cp       = r0;
        *(float4*)(cp + 4) = r1;
    }
}

// ---------------------------------------------------------------------------
// Copy input kv caches to output regions (slots not in slot_mapping keep input)
// ---------------------------------------------------------------------------
__global__ void copy_cache(const float4* __restrict__ k_in, const float4* __restrict__ v_in,
                           float4* __restrict__ k_out, float4* __restrict__ v_out, int n4)
{
    int i = blockIdx.x * blockDim.x + threadIdx.x;
    if (i < n4) { k_out[i] = k_in[i]; v_out[i] = v_in[i]; }
}

// ---------------------------------------------------------------------------
// RoPE in place on q (12 heads) and k (2 heads) of qkv, then scatter k,v into caches.
// One block per token.
// ---------------------------------------------------------------------------
__global__ void rope_scatter(float* __restrict__ qkv, const float* __restrict__ cosp,
                             const float* __restrict__ sinp, const int* __restrict__ slot_mapping,
                             float* __restrict__ kc, float* __restrict__ vc)
{
    int row = blockIdx.x;            // token 0..8191
    int tid = threadIdx.x;           // 256
    const float* c = cosp + (size_t)row * D_;
    const float* s = sinp + (size_t)row * D_;
    float* base = qkv + (size_t)row * QKV_N;

    // q heads 0..11 at offsets 0..1535, k heads at 1536,1664 -> heads 12,13
    for (int i = tid; i < 14 * 64; i += blockDim.x) {
        int hh = i >> 6, d = i & 63;
        float* p = base + hh * D_;
        float x1 = p[d], x2 = p[d + 64];
        float c1 = c[d], s1 = s[d];
        float c2 = c[d + 64], s2 = s[d + 64];
        p[d]      = x1 * c1 - x2 * s1;
        p[d + 64] = x2 * c2 + x1 * s2;
    }
    __syncthreads();
    int slot = slot_mapping[row];
    for (int i = tid; i < HKV_ * D_; i += blockDim.x) {
        kc[(size_t)slot * (HKV_*D_) + i] = base[H_*D_ + i];
        vc[(size_t)slot * (HKV_*D_) + i] = base[H_*D_ + HKV_*D_ + i];
    }
}

// ---------------------------------------------------------------------------
// Causal flash attention, fp32. One block per (q-tile 64, head, batch).
// Online softmax, 64x64 KV tiles, D=128.
// ---------------------------------------------------------------------------
#define AT_THREADS 256
#define ATT_SMEM_FLOATS (128*68*2 + 64*132 + 64*68 + 192)
#define ATT_SMEM_BYTES  (ATT_SMEM_FLOATS * 4)

__global__ __launch_bounds__(AT_THREADS, 1)
void attn_kernel(const float* __restrict__ qkv, float* __restrict__ ao)
{
    extern __shared__ float sm[];
    float* Qs  = sm;                      // [128][68]  d-major
    float* Ks  = Qs + 128*68;             // [128][68]  d-major
    float* Vs  = Ks + 128*68;             // [64][132]  n-major
    float* Ps  = Vs + 64*132;             // [64][68]
    float* m_s = Ps + 64*68;              // [64]
    float* l_s = m_s + 64;                // [64]
    float* sc_s= l_s + 64;                // [64]

    int qt = blockIdx.x, h = blockIdx.y, b = blockIdx.z;
    int kvh = h / NGROUPS_;
    int q0 = qt * 64;
    int tid = threadIdx.x;
    int tx = tid & 15;    // 0..15
    int ty = tid >> 4;    // 0..15

    // Load Q tile transposed into Qs[d][m]
    for (int idx = tid; idx < 64 * 32; idx += AT_THREADS) {
        int m = idx & 63, d4 = idx >> 6;
        int d = d4 * 4;
        float4 v = *(const float4*)(qkv + ((size_t)(b * S_ + q0 + m)) * QKV_N + h * D_ + d);
        Qs[(d+0)*68 + m] = v.x; Qs[(d+1)*68 + m] = v.y;
        Qs[(d+2)*68 + m] = v.z; Qs[(d+3)*68 + m] = v.w;
    }
    if (tid < 64) { m_s[tid] = -INFINITY; l_s[tid] = 0.f; }

    float o[4][8];
    #pragma unroll
    for (int i = 0; i < 4; i++)
        #pragma unroll
        for (int j = 0; j < 8; j++) o[i][j] = 0.f;

    __syncthreads();

    const float scale = 0.08838834764831845f; // 1/sqrt(128)

    for (int t = 0; t <= qt; t++) {
        int k0 = t * 64;

        // Load K tile transposed into Ks[d][n]
        for (int idx = tid; idx < 64 * 32; idx += AT_THREADS) {
            int n = idx & 63, d4 = idx >> 6;
            int d = d4 * 4;
            float4 v = *(const float4*)(qkv + ((size_t)(b * S_ + k0 + n)) * QKV_N
                                        + H_*D_ + kvh * D_ + d);
            Ks[(d+0)*68 + n] = v.x; Ks[(d+1)*68 + n] = v.y;
            Ks[(d+2)*68 + n] = v.z; Ks[(d+3)*68 + n] = v.w;
        }
        // Load V tile into Vs[n][d]
        for (int idx = tid; idx < 64 * 32; idx += AT_THREADS) {
            int n = idx >> 5, d4 = idx & 31;
            *(float4*)&Vs[n*132 + d4*4] =
                *(const float4*)(qkv + ((size_t)(b * S_ + k0 + n)) * QKV_N
                                 + H_*D_ + HKV_*D_ + kvh * D_ + d4*4);
        }
        __syncthreads();

        // Phase 1: scores S = Q K^T (each thread 4x4)
        float s4[4][4];
        #pragma unroll
        for (int i = 0; i < 4; i++)
            #pragma unroll
            for (int j = 0; j < 4; j++) s4[i][j] = 0.f;

        #pragma unroll 8
        for (int d = 0; d < 128; d++) {
            float4 a = *(const float4*)&Qs[d*68 + ty*4];
            float4 bb = *(const float4*)&Ks[d*68 + tx*4];
            float ra[4] = {a.x, a.y, a.z, a.w};
            float rb[4] = {bb.x, bb.y, bb.z, bb.w};
            #pragma unroll
            for (int i = 0; i < 4; i++)
                #pragma unroll
                for (int j = 0; j < 4; j++)
                    s4[i][j] = fmaf(ra[i], rb[j], s4[i][j]);
        }

        // scale + causal mask
        #pragma unroll
        for (int i = 0; i < 4; i++) {
            int qi = q0 + ty*4 + i;
            #pragma unroll
            for (int j = 0; j < 4; j++) {
                int ki = k0 + tx*4 + j;
                float v = s4[i][j] * scale;
                s4[i][j] = (ki > qi) ? -1e30f : v;
            }
        }

        // Phase 2: online softmax per row (16 lanes per row share one half-warp)
        #pragma unroll
        for (int i = 0; i < 4; i++) {
            int row = ty*4 + i;
            float mx = fmaxf(fmaxf(s4[i][0], s4[i][1]), fmaxf(s4[i][2], s4[i][3]));
            #pragma unroll
            for (int off = 8; off > 0; off >>= 1)
                mx = fmaxf(mx, __shfl_xor_sync(0xffffffffu, mx, off, 16));
            float oldm = m_s[row];
            float nm = fmaxf(oldm, mx);
            float psum = 0.f;
            #pragma unroll
            for (int j = 0; j < 4; j++) {
                float p = __expf(s4[i][j] - nm);
                Ps[row*68 + tx*4 + j] = p;
                psum += p;
            }
            #pragma unroll
            for (int off = 8; off > 0; off >>= 1)
                psum += __shfl_xor_sync(0xffffffffu, psum, off, 16);
            if (tx == 0) {
                float sc = __expf(oldm - nm);
                sc_s[row] = sc;
                l_s[row] = l_s[row] * sc + psum;
                m_s[row] = nm;
            }
        }
        __syncthreads();

        // Phase 3: O = O*sc + P @ V (each thread 4 rows x 8 cols)
        #pragma unroll
        for (int i = 0; i < 4; i++) {
            float f = sc_s[ty*4 + i];
            #pragma unroll
            for (int j = 0; j < 8; j++) o[i][j] *= f;
        }
        #pragma unroll 2
        for (int n = 0; n < 64; n++) {
            float4 v0 = *(const float4*)&Vs[n*132 + tx*8];
            float4 v1 = *(const float4*)&Vs[n*132 + tx*8 + 4];
            #pragma unroll
            for (int i = 0; i < 4; i++) {
                float p = Ps[(ty*4 + i)*68 + n];
                o[i][0] = fmaf(p, v0.x, o[i][0]);
                o[i][1] = fmaf(p, v0.y, o[i][1]);
                o[i][2] = fmaf(p, v0.z, o[i][2]);
                o[i][3] = fmaf(p, v0.w, o[i][3]);
                o[i][4] = fmaf(p, v1.x, o[i][4]);
                o[i][5] = fmaf(p, v1.y, o[i][5]);
                o[i][6] = fmaf(p, v1.z, o[i][6]);
                o[i][7] = fmaf(p, v1.w, o[i][7]);
            }
        }
        __syncthreads();
    }

    // Epilogue: divide by l, write to ao (b,s,h,d)
    #pragma unroll
    for (int i = 0; i < 4; i++) {
        int row = ty*4 + i;
        float inv = 1.0f / l_s[row];
        float* op = ao + ((size_t)(b * S_ + q0 + row)) * HID_ + h * D_ + tx*8;
        float4 r0, r1;
        r0.x = o[i][0]*inv; r0.y = o[i][1]*inv; r0.z = o[i][2]*inv; r0.w = o[i][3]*inv;
        r1.x = o[i][4]*inv; r1.y = o[i][5]*inv; r1.z = o[i][6]*inv; r1.w = o[i][7]*inv;
        *(float4*)op       = r0;
        *(float4*)(op + 4) = r1;
    }
}

// ---------------------------------------------------------------------------
extern "C" void kernel_launch(void* const* d_in, const int* in_sizes, int n_in,
                              void* d_out, int out_size)
{
    const float* x     = (const float*)d_in[0];
    const float* cosp  = (const float*)d_in[1];
    const float* sinp  = (const float*)d_in[2];
    const float* kci   = (const float*)d_in[3];
    const float* vci   = (const float*)d_in[4];
    const int*   slot  = (const int*)  d_in[5];
    const float* Wqkv  = (const float*)d_in[6];
    const float* bqkv  = (const float*)d_in[7];
    const float* Wo    = (const float*)d_in[8];
    // d_in[9] = is_prefill (always 1)

    float* out = (float*)d_out;
    float* kc  = out + (size_t)NTOK * HID_;                 // 12,582,912
    float* vc  = kc  + (size_t)NSLOTS_ * HKV_ * D_;         // +4,194,304

    float* qkv; cudaGetSymbolAddress((void**)&qkv, g_qkv);
    float* ao;  cudaGetSymbolAddress((void**)&ao,  g_ao);

    cudaFuncSetAttribute(attn_kernel, cudaFuncAttributeMaxDynamicSharedMemorySize,
                         ATT_SMEM_BYTES);

    // 1) QKV projection: (8192,2048) = x(8192,1536) @ Wqkv(2048,1536)^T + b
    gemm_nt_bias<<<dim3(QKV_N / GBN, NTOK / GBM), 256>>>(x, Wqkv, bqkv, qkv,
                                                         NTOK, QKV_N, HID_);

    // 2) Copy input caches to output (slots not written keep input values)
    {
        int n4 = NSLOTS_ * HKV_ * D_ / 4;   // 1,048,576 float4 each
        copy_cache<<<(n4 + 255) / 256, 256>>>((const float4*)kci, (const float4*)vci,
                                              (float4*)kc, (float4*)vc, n4);
    }

    // 3) RoPE on q,k in place + scatter k,v into caches
    rope_scatter<<<NTOK, 256>>>(qkv, cosp, sinp, slot, kc, vc);

    // 4) Causal GQA flash attention
    attn_kernel<<<dim3(S_ / 64, H_, B_), AT_THREADS, ATT_SMEM_BYTES>>>(qkv, ao);

    // 5) Output projection: out(8192,1536) = ao @ Wo(1536,1536)^T
    gemm_nt_bias<<<dim3(HID_ / GBN, NTOK / GBM), 256>>>(ao, Wo, nullptr, out,
                                                        NTOK, HID_, HID_);
}

// round 5
// speedup vs baseline: 1.4098x; 1.4098x over previous
#include <cuda_runtime.h>
#include <cuda_bf16.h>
#include <math.h>
#include <stdint.h>

// Problem constants
#define B_    4
#define S_    2048
#define HID_  1536
#define H_    12
#define HKV_  2
#define D_    128
#define NGROUPS_ 6
#define NSLOTS_ 16384
#define NTOK  (B_ * S_)            // 8192
#define QKV_N (H_*D_ + 2*HKV_*D_)  // 2048

// Scratch (device globals; allocation in kernel_launch is forbidden)
__device__ float g_qkv[(size_t)NTOK * QKV_N];   // 64 MB
__device__ float g_ao [(size_t)NTOK * HID_];    // 48 MB
__device__ __nv_bfloat16 g_xhi [(size_t)NTOK * HID_];
__device__ __nv_bfloat16 g_xlo [(size_t)NTOK * HID_];
__device__ __nv_bfloat16 g_wqhi[(size_t)QKV_N * HID_];
__device__ __nv_bfloat16 g_wqlo[(size_t)QKV_N * HID_];
__device__ __nv_bfloat16 g_wohi[(size_t)HID_ * HID_];
__device__ __nv_bfloat16 g_wolo[(size_t)HID_ * HID_];
__device__ __nv_bfloat16 g_aohi[(size_t)NTOK * HID_];
__device__ __nv_bfloat16 g_aolo[(size_t)NTOK * HID_];

// ---------------------------------------------------------------------------
// Portable PTX helpers (no sm_103a-gated instructions!)
// ---------------------------------------------------------------------------
__device__ __forceinline__ uint32_t s2u(const void* p) {
    uint32_t a;
    asm("{ .reg .u64 t; cvta.to.shared.u64 t, %1; cvt.u32.u64 %0, t; }"
        : "=r"(a) : "l"(p));
    return a;
}

#define CP_ASYNC16(dst, src) \
    asm volatile("cp.async.cg.shared.global [%0], [%1], 16;" \
                 :: "r"(dst), "l"(src))
#define CP_COMMIT() asm volatile("cp.async.commit_group;")
#define CP_WAIT1()  asm volatile("cp.async.wait_group 1;")
#define CP_WAIT0()  asm volatile("cp.async.wait_group 0;")

#define LDSM4(r0, r1, r2, r3, addr) \
    asm volatile("ldmatrix.sync.aligned.m8n8.x4.shared.b16 {%0,%1,%2,%3}, [%4];" \
                 : "=r"(r0), "=r"(r1), "=r"(r2), "=r"(r3) : "r"(addr))

#define MMA16816(d, a, b) \
    asm volatile("mma.sync.aligned.m16n8k16.row.col.f32.bf16.bf16.f32 " \
                 "{%0,%1,%2,%3}, {%4,%5,%6,%7}, {%8,%9}, {%0,%1,%2,%3};" \
                 : "+f"((d)[0]), "+f"((d)[1]), "+f"((d)[2]), "+f"((d)[3]) \
                 : "r"((a)[0]), "r"((a)[1]), "r"((a)[2]), "r"((a)[3]), \
                   "r"((b)[0]), "r"((b)[1]))

// smem chunk swizzle: row r (64B rows = 4x 16B chunks), chunk c
__device__ __forceinline__ uint32_t swz(int r, int c) {
    return (uint32_t)(r * 64 + ((c ^ ((r >> 1) & 3)) << 4));
}

// ---------------------------------------------------------------------------
// Split fp32 -> (bf16 hi, bf16 lo)
// ---------------------------------------------------------------------------
__global__ void split_bf16(const float4* __restrict__ in,
                           uint2* __restrict__ hi, uint2* __restrict__ lo, int n4)
{
    int i = blockIdx.x * blockDim.x + threadIdx.x;
    if (i >= n4) return;
    float4 v = in[i];
    __nv_bfloat16 h0 = __float2bfloat16(v.x), h1 = __float2bfloat16(v.y);
    __nv_bfloat16 h2 = __float2bfloat16(v.z), h3 = __float2bfloat16(v.w);
    __nv_bfloat16 l0 = __float2bfloat16(v.x - __bfloat162float(h0));
    __nv_bfloat16 l1 = __float2bfloat16(v.y - __bfloat162float(h1));
    __nv_bfloat16 l2 = __float2bfloat16(v.z - __bfloat162float(h2));
    __nv_bfloat16 l3 = __float2bfloat16(v.w - __bfloat162float(h3));
    uint2 hv, lv;
    hv.x = (uint32_t)__bfloat16_as_ushort(h0) | ((uint32_t)__bfloat16_as_ushort(h1) << 16);
    hv.y = (uint32_t)__bfloat16_as_ushort(h2) | ((uint32_t)__bfloat16_as_ushort(h3) << 16);
    lv.x = (uint32_t)__bfloat16_as_ushort(l0) | ((uint32_t)__bfloat16_as_ushort(l1) << 16);
    lv.y = (uint32_t)__bfloat16_as_ushort(l2) | ((uint32_t)__bfloat16_as_ushort(l3) << 16);
    hi[i] = hv;
    lo[i] = lv;
}

// ---------------------------------------------------------------------------
// mma.sync GEMM: C[M,N] = Ahi*Bhi^T + Ahi*Blo^T + Alo*Bhi^T (+bias)
// A*,B* bf16 row-major [rows, K]. 128x128x32 tile, 256 thr, 8 warps (4x2),
// cp.async double buffer, swizzled ldmatrix.
// ---------------------------------------------------------------------------
#define MT_BK     32                 // K halves per tile
#define MT_TILE   8192               // bytes per matrix variant (128 rows * 64B)
#define MT_STAGE  32768              // Ahi+Alo+Bhi+Blo
#define MT_SMEM   (2 * MT_STAGE)     // 64 KB

__device__ __forceinline__ void mt_stage_load(
    const __nv_bfloat16* __restrict__ Ahi, const __nv_bfloat16* __restrict__ Alo,
    const __nv_bfloat16* __restrict__ Bhi, const __nv_bfloat16* __restrict__ Blo,
    int m0, int n0, int K, int k0, uint32_t sstage, int tid)
{
    #pragma unroll
    for (int it = 0; it < 8; it++) {
        int idx = tid + it * 256;       // 0..2047
        int t   = idx >> 9;             // 0..3: Ahi, Alo, Bhi, Blo
        int rem = idx & 511;
        int r   = rem >> 2;             // 0..127
        int c   = rem & 3;              // chunk
        const __nv_bfloat16* base = (t == 0) ? Ahi : (t == 1) ? Alo
                                  : (t == 2) ? Bhi : Blo;
        int row0 = (t < 2) ? m0 : n0;
        const char* src = (const char*)(base + (size_t)(row0 + r) * K + k0) + c * 16;
        uint32_t dst = sstage + (uint32_t)t * MT_TILE + swz(r, c);
        CP_ASYNC16(dst, src);
    }
}

__global__ __launch_bounds__(256)
void gemm_mma(const __nv_bfloat16* __restrict__ Ahi, const __nv_bfloat16* __restrict__ Alo,
              const __nv_bfloat16* __restrict__ Bhi, const __nv_bfloat16* __restrict__ Blo,
              const float* __restrict__ bias, float* __restrict__ C,
              int M, int N, int K)
{
    extern __shared__ char smg[];
    uint32_t sb = s2u(smg);
    int tid = threadIdx.x;
    int wid = tid >> 5, lane = tid & 31;
    int wm = wid & 3, wn = wid >> 2;       // 4 x 2 warp grid
    int mbase = wm * 32, nbase = wn * 64;
    int m0 = blockIdx.y * 128, n0 = blockIdx.x * 128;

    float acc[2][8][4];
    #pragma unroll
    for (int i = 0; i < 2; i++)
        #pragma unroll
        for (int j = 0; j < 8; j++)
            #pragma unroll
            for (int q = 0; q < 4; q++) acc[i][j][q] = 0.f;

    const int nkt = K >> 5;   // K / 32

    mt_stage_load(Ahi, Alo, Bhi, Blo, m0, n0, K, 0, sb, tid);
    CP_COMMIT();

    int lrow = lane & 15;     // ldmatrix row within 16
    int lsel = lane >> 4;     // 0: k0-7 chunk, 1: k8-15 chunk

    for (int kt = 0; kt < nkt; kt++) {
        uint32_t sbuf = sb + (uint32_t)(kt & 1) * MT_STAGE;
        if (kt + 1 < nkt) {
            mt_stage_load(Ahi, Alo, Bhi, Blo, m0, n0, K, (kt + 1) << 5,
                          sb + (uint32_t)((kt + 1) & 1) * MT_STAGE, tid);
            CP_COMMIT();
            CP_WAIT1();
        } else {
            CP_WAIT0();
        }
        __syncthreads();

        #pragma unroll
        for (int ks = 0; ks < 2; ks++) {
            int kc = ks * 2;
            uint32_t ah[2][4], al[2][4], bh[8][2], bl[8][2];
            // A fragments (2 x m16)
            #pragma unroll
            for (int f = 0; f < 2; f++) {
                int r = mbase + f * 16 + lrow;
                int c = kc + lsel;
                LDSM4(ah[f][0], ah[f][1], ah[f][2], ah[f][3], sbuf + swz(r, c));
                LDSM4(al[f][0], al[f][1], al[f][2], al[f][3],
                      sbuf + MT_TILE + swz(r, c));
            }
            // B fragments (8 x n8, loaded as 4 x ldmatrix.x4 per variant)
            #pragma unroll
            for (int g = 0; g < 4; g++) {
                int r = nbase + g * 16 + lrow;
                int c = kc + lsel;
                uint32_t r0, r1, r2, r3;
                LDSM4(r0, r1, r2, r3, sbuf + 2 * MT_TILE + swz(r, c));
                bh[2*g][0] = r0; bh[2*g][1] = r2;
                bh[2*g+1][0] = r1; bh[2*g+1][1] = r3;
                LDSM4(r0, r1, r2, r3, sbuf + 3 * MT_TILE + swz(r, c));
                bl[2*g][0] = r0; bl[2*g][1] = r2;
                bl[2*g+1][0] = r1; bl[2*g+1][1] = r3;
            }
            // 3-pass compensated MMAs
            #pragma unroll
            for (int mi = 0; mi < 2; mi++)
                #pragma unroll
                for (int nj = 0; nj < 8; nj++) {
                    MMA16816(acc[mi][nj], ah[mi], bh[nj]);
                    MMA16816(acc[mi][nj], ah[mi], bl[nj]);
                    MMA16816(acc[mi][nj], al[mi], bh[nj]);
                }
        }
        __syncthreads();
    }

    // Epilogue
    int erow = lane >> 2;          // 0..7
    int ecol = (lane & 3) * 2;     // 0,2,4,6
    #pragma unroll
    for (int mi = 0; mi < 2; mi++) {
        #pragma unroll
        for (int nj = 0; nj < 8; nj++) {
            int col = n0 + nbase + nj * 8 + ecol;
            float b0 = bias ? bias[col]     : 0.f;
            float b1 = bias ? bias[col + 1] : 0.f;
            int r0 = m0 + mbase + mi * 16 + erow;
            float2 v0 = make_float2(acc[mi][nj][0] + b0, acc[mi][nj][1] + b1);
            float2 v1 = make_float2(acc[mi][nj][2] + b0, acc[mi][nj][3] + b1);
            *(float2*)(C + (size_t)r0 * N + col)       = v0;
            *(float2*)(C + (size_t)(r0 + 8) * N + col) = v1;
        }
    }
}

// ---------------------------------------------------------------------------
// Copy input kv caches to output regions
// ---------------------------------------------------------------------------
__global__ void copy_cache(const float4* __restrict__ k_in, const float4* __restrict__ v_in,
                           float4* __restrict__ k_out, float4* __restrict__ v_out, int n4)
{
    int i = blockIdx.x * blockDim.x + threadIdx.x;
    if (i < n4) { k_out[i] = k_in[i]; v_out[i] = v_in[i]; }
}

// ---------------------------------------------------------------------------
// RoPE in place on q,k of qkv, then scatter k,v into caches. One block/token.
// ---------------------------------------------------------------------------
__global__ void rope_scatter(float* __restrict__ qkv, const float* __restrict__ cosp,
                             const float* __restrict__ sinp, const int* __restrict__ slot_mapping,
                             float* __restrict__ kc, float* __restrict__ vc)
{
    int row = blockIdx.x;
    int tid = threadIdx.x;
    const float* c = cosp + (size_t)row * D_;
    const float* s = sinp + (size_t)row * D_;
    float* base = qkv + (size_t)row * QKV_N;

    for (int i = tid; i < 14 * 64; i += blockDim.x) {
        int hh = i >> 6, d = i & 63;
        float* p = base + hh * D_;
        float x1 = p[d], x2 = p[d + 64];
        float c1 = c[d], s1 = s[d];
        float c2 = c[d + 64], s2 = s[d + 64];
        p[d]      = x1 * c1 - x2 * s1;
        p[d + 64] = x2 * c2 + x1 * s2;
    }
    __syncthreads();
    int slot = slot_mapping[row];
    for (int i = tid; i < HKV_ * D_; i += blockDim.x) {
        kc[(size_t)slot * (HKV_*D_) + i] = base[H_*D_ + i];
        vc[(size_t)slot * (HKV_*D_) + i] = base[H_*D_ + HKV_*D_ + i];
    }
}

// ---------------------------------------------------------------------------
// Causal flash attention, fp32 (unchanged this round).
// ---------------------------------------------------------------------------
#define AT_THREADS 256
#define ATT_SMEM_FLOATS (128*68*2 + 64*132 + 64*68 + 192)
#define ATT_SMEM_BYTES  (ATT_SMEM_FLOATS * 4)

__global__ __launch_bounds__(AT_THREADS, 1)
void attn_kernel(const float* __restrict__ qkv, float* __restrict__ ao)
{
    extern __shared__ float sm[];
    float* Qs  = sm;
    float* Ks  = Qs + 128*68;
    float* Vs  = Ks + 128*68;
    float* Ps  = Vs + 64*132;
    float* m_s = Ps + 64*68;
    float* l_s = m_s + 64;
    float* sc_s= l_s + 64;

    int qt = blockIdx.x, h = blockIdx.y, b = blockIdx.z;
    int kvh = h / NGROUPS_;
    int q0 = qt * 64;
    int tid = threadIdx.x;
    int tx = tid & 15;
    int ty = tid >> 4;

    for (int idx = tid; idx < 64 * 32; idx += AT_THREADS) {
        int m = idx & 63, d4 = idx >> 6;
        int d = d4 * 4;
        float4 v = *(const float4*)(qkv + ((size_t)(b * S_ + q0 + m)) * QKV_N + h * D_ + d);
        Qs[(d+0)*68 + m] = v.x; Qs[(d+1)*68 + m] = v.y;
        Qs[(d+2)*68 + m] = v.z; Qs[(d+3)*68 + m] = v.w;
    }
    if (tid < 64) { m_s[tid] = -INFINITY; l_s[tid] = 0.f; }

    float o[4][8];
    #pragma unroll
    for (int i = 0; i < 4; i++)
        #pragma unroll
        for (int j = 0; j < 8; j++) o[i][j] = 0.f;

    __syncthreads();

    const float scale = 0.08838834764831845f;

    for (int t = 0; t <= qt; t++) {
        int k0 = t * 64;
        for (int idx = tid; idx < 64 * 32; idx += AT_THREADS) {
            int n = idx & 63, d4 = idx >> 6;
            int d = d4 * 4;
            float4 v = *(const float4*)(qkv + ((size_t)(b * S_ + k0 + n)) * QKV_N
                                        + H_*D_ + kvh * D_ + d);
            Ks[(d+0)*68 + n] = v.x; Ks[(d+1)*68 + n] = v.y;
            Ks[(d+2)*68 + n] = v.z; Ks[(d+3)*68 + n] = v.w;
        }
        for (int idx = tid; idx < 64 * 32; idx += AT_THREADS) {
            int n = idx >> 5, d4 = idx & 31;
            *(float4*)&Vs[n*132 + d4*4] =
                *(const float4*)(qkv + ((size_t)(b * S_ + k0 + n)) * QKV_N
                                 + H_*D_ + HKV_*D_ + kvh * D_ + d4*4);
        }
        __syncthreads();

        float s4[4][4];
        #pragma unroll
        for (int i = 0; i < 4; i++)
            #pragma unroll
            for (int j = 0; j < 4; j++) s4[i][j] = 0.f;

        #pragma unroll 8
        for (int d = 0; d < 128; d++) {
            float4 a = *(const float4*)&Qs[d*68 + ty*4];
            float4 bb = *(const float4*)&Ks[d*68 + tx*4];
            float ra[4] = {a.x, a.y, a.z, a.w};
            float rb[4] = {bb.x, bb.y, bb.z, bb.w};
            #pragma unroll
            for (int i = 0; i < 4; i++)
                #pragma unroll
                for (int j = 0; j < 4; j++)
                    s4[i][j] = fmaf(ra[i], rb[j], s4[i][j]);
        }

        #pragma unroll
        for (int i = 0; i < 4; i++) {
            int qi = q0 + ty*4 + i;
            #pragma unroll
            for (int j = 0; j < 4; j++) {
                int ki = k0 + tx*4 + j;
                float v = s4[i][j] * scale;
                s4[i][j] = (ki > qi) ? -1e30f : v;
            }
        }

        #pragma unroll
        for (int i = 0; i < 4; i++) {
            int row = ty*4 + i;
            float mx = fmaxf(fmaxf(s4[i][0], s4[i][1]), fmaxf(s4[i][2], s4[i][3]));
            #pragma unroll
            for (int off = 8; off > 0; off >>= 1)
                mx = fmaxf(mx, __shfl_xor_sync(0xffffffffu, mx, off, 16));
            float oldm = m_s[row];
            float nm = fmaxf(oldm, mx);
            float psum = 0.f;
            #pragma unroll
            for (int j = 0; j < 4; j++) {
                float p = __expf(s4[i][j] - nm);
                Ps[row*68 + tx*4 + j] = p;
                psum += p;
            }
            #pragma unroll
            for (int off = 8; off > 0; off >>= 1)
                psum += __shfl_xor_sync(0xffffffffu, psum, off, 16);
            if (tx == 0) {
                float sc = __expf(oldm - nm);
                sc_s[row] = sc;
                l_s[row] = l_s[row] * sc + psum;
                m_s[row] = nm;
            }
        }
        __syncthreads();

        #pragma unroll
        for (int i = 0; i < 4; i++) {
            float f = sc_s[ty*4 + i];
            #pragma unroll
            for (int j = 0; j < 8; j++) o[i][j] *= f;
        }
        #pragma unroll 2
        for (int n = 0; n < 64; n++) {
            float4 v0 = *(const float4*)&Vs[n*132 + tx*8];
            float4 v1 = *(const float4*)&Vs[n*132 + tx*8 + 4];
            #pragma unroll
            for (int i = 0; i < 4; i++) {
                float p = Ps[(ty*4 + i)*68 + n];
                o[i][0] = fmaf(p, v0.x, o[i][0]);
                o[i][1] = fmaf(p, v0.y, o[i][1]);
                o[i][2] = fmaf(p, v0.z, o[i][2]);
                o[i][3] = fmaf(p, v0.w, o[i][3]);
                o[i][4] = fmaf(p, v1.x, o[i][4]);
                o[i][5] = fmaf(p, v1.y, o[i][5]);
                o[i][6] = fmaf(p, v1.z, o[i][6]);
                o[i][7] = fmaf(p, v1.w, o[i][7]);
            }
        }
        __syncthreads();
    }

    #pragma unroll
    for (int i = 0; i < 4; i++) {
        int row = ty*4 + i;
        float inv = 1.0f / l_s[row];
        float* op = ao + ((size_t)(b * S_ + q0 + row)) * HID_ + h * D_ + tx*8;
        float4 r0, r1;
        r0.x = o[i][0]*inv; r0.y = o[i][1]*inv; r0.z = o[i][2]*inv; r0.w = o[i][3]*inv;
        r1.x = o[i][4]*inv; r1.y = o[i][5]*inv; r1.z = o[i][6]*inv; r1.w = o[i][7]*inv;
        *(float4*)op       = r0;
        *(float4*)(op + 4) = r1;
    }
}

// ---------------------------------------------------------------------------
extern "C" void kernel_launch(void* const* d_in, const int* in_sizes, int n_in,
                              void* d_out, int out_size)
{
    const float* x     = (const float*)d_in[0];
    const float* cosp  = (const float*)d_in[1];
    const float* sinp  = (const float*)d_in[2];
    const float* kci   = (const float*)d_in[3];
    const float* vci   = (const float*)d_in[4];
    const int*   slot  = (const int*)  d_in[5];
    const float* Wqkv  = (const float*)d_in[6];
    const float* bqkv  = (const float*)d_in[7];
    const float* Wo    = (const float*)d_in[8];

    float* out = (float*)d_out;
    float* kc  = out + (size_t)NTOK * HID_;
    float* vc  = kc  + (size_t)NSLOTS_ * HKV_ * D_;

    float* qkv; cudaGetSymbolAddress((void**)&qkv, g_qkv);
    float* ao;  cudaGetSymbolAddress((void**)&ao,  g_ao);
    __nv_bfloat16 *xhi, *xlo, *wqhi, *wqlo, *wohi, *wolo, *aohi, *aolo;
    cudaGetSymbolAddress((void**)&xhi,  g_xhi);
    cudaGetSymbolAddress((void**)&xlo,  g_xlo);
    cudaGetSymbolAddress((void**)&wqhi, g_wqhi);
    cudaGetSymbolAddress((void**)&wqlo, g_wqlo);
    cudaGetSymbolAddress((void**)&wohi, g_wohi);
    cudaGetSymbolAddress((void**)&wolo, g_wolo);
    cudaGetSymbolAddress((void**)&aohi, g_aohi);
    cudaGetSymbolAddress((void**)&aolo, g_aolo);

    cudaFuncSetAttribute(attn_kernel, cudaFuncAttributeMaxDynamicSharedMemorySize,
                         ATT_SMEM_BYTES);
    cudaFuncSetAttribute(gemm_mma, cudaFuncAttributeMaxDynamicSharedMemorySize,
                         MT_SMEM);

    // 0) fp32 -> bf16 hi/lo splits for GEMM operands
    {
        int n4 = NTOK * HID_ / 4;
        split_bf16<<<(n4 + 255) / 256, 256>>>((const float4*)x, (uint2*)xhi, (uint2*)xlo, n4);
        n4 = QKV_N * HID_ / 4;
        split_bf16<<<(n4 + 255) / 256, 256>>>((const float4*)Wqkv, (uint2*)wqhi, (uint2*)wqlo, n4);
        n4 = HID_ * HID_ / 4;
        split_bf16<<<(n4 + 255) / 256, 256>>>((const float4*)Wo, (uint2*)wohi, (uint2*)wolo, n4);
    }

    // 1) QKV projection (tensor cores, 3-MMA compensated bf16)
    gemm_mma<<<dim3(QKV_N / 128, NTOK / 128), 256, MT_SMEM>>>(
        xhi, xlo, wqhi, wqlo, bqkv, qkv, NTOK, QKV_N, HID_);

    // 2) Copy input caches to output
    {
        int n4 = NSLOTS_ * HKV_ * D_ / 4;
        copy_cache<<<(n4 + 255) / 256, 256>>>((const float4*)kci, (const float4*)vci,
                                              (float4*)kc, (float4*)vc, n4);
    }

    // 3) RoPE + scatter
    rope_scatter<<<NTOK, 256>>>(qkv, cosp, sinp, slot, kc, vc);

    // 4) Causal GQA flash attention (fp32)
    attn_kernel<<<dim3(S_ / 64, H_, B_), AT_THREADS, ATT_SMEM_BYTES>>>(qkv, ao);

    // 5) Split attention output, then out projection (tensor cores)
    {
        int n4 = NTOK * HID_ / 4;
        split_bf16<<<(n4 + 255) / 256, 256>>>((const float4*)ao, (uint2*)aohi, (uint2*)aolo, n4);
    }
    gemm_mma<<<dim3(HID_ / 128, NTOK / 128), 256, MT_SMEM>>>(
        aohi, aolo, wohi, wolo, nullptr, out, NTOK, HID_, HID_);
}

// round 7
// speedup vs baseline: 3.0300x; 2.1492x over previous
#include <cuda_runtime.h>
#include <cuda_bf16.h>
#include <math.h>
#include <stdint.h>

// Problem constants
#define B_    4
#define S_    2048
#define HID_  1536
#define H_    12
#define HKV_  2
#define D_    128
#define NGROUPS_ 6
#define NSLOTS_ 16384
#define NTOK  (B_ * S_)            // 8192
#define QKV_N (H_*D_ + 2*HKV_*D_)  // 2048

// Scratch (device globals; allocation in kernel_launch is forbidden)
__device__ float g_qkv[(size_t)NTOK * QKV_N];   // 64 MB
__device__ float g_ao [(size_t)NTOK * HID_];    // 48 MB
__device__ __nv_bfloat16 g_xhi [(size_t)NTOK * HID_];
__device__ __nv_bfloat16 g_xlo [(size_t)NTOK * HID_];
__device__ __nv_bfloat16 g_wqhi[(size_t)QKV_N * HID_];
__device__ __nv_bfloat16 g_wqlo[(size_t)QKV_N * HID_];
__device__ __nv_bfloat16 g_wohi[(size_t)HID_ * HID_];
__device__ __nv_bfloat16 g_wolo[(size_t)HID_ * HID_];
__device__ __nv_bfloat16 g_aohi[(size_t)NTOK * HID_];
__device__ __nv_bfloat16 g_aolo[(size_t)NTOK * HID_];
// Attention operand buffers (hi/lo splits)
__device__ __nv_bfloat16 g_qhi[(size_t)B_ * H_ * S_ * D_];
__device__ __nv_bfloat16 g_qlo[(size_t)B_ * H_ * S_ * D_];
__device__ __nv_bfloat16 g_khi[(size_t)B_ * HKV_ * S_ * D_];
__device__ __nv_bfloat16 g_klo[(size_t)B_ * HKV_ * S_ * D_];
__device__ __nv_bfloat16 g_vhi[(size_t)B_ * HKV_ * D_ * S_];  // transposed [d][s]
__device__ __nv_bfloat16 g_vlo[(size_t)B_ * HKV_ * D_ * S_];

// ---------------------------------------------------------------------------
// Portable PTX helpers
// ---------------------------------------------------------------------------
__device__ __forceinline__ uint32_t s2u(const void* p) {
    uint32_t a;
    asm("{ .reg .u64 t; cvta.to.shared.u64 t, %1; cvt.u32.u64 %0, t; }"
        : "=r"(a) : "l"(p));
    return a;
}

#define CP_ASYNC16(dst, src) \
    asm volatile("cp.async.cg.shared.global [%0], [%1], 16;" \
                 :: "r"(dst), "l"(src))
#define CP_COMMIT() asm volatile("cp.async.commit_group;")
#define CP_WAIT1()  asm volatile("cp.async.wait_group 1;")
#define CP_WAIT0()  asm volatile("cp.async.wait_group 0;")

#define LDSM4(r0, r1, r2, r3, addr) \
    asm volatile("ldmatrix.sync.aligned.m8n8.x4.shared.b16 {%0,%1,%2,%3}, [%4];" \
                 : "=r"(r0), "=r"(r1), "=r"(r2), "=r"(r3) : "r"(addr))

#define MMA16816(d, a, b) \
    asm volatile("mma.sync.aligned.m16n8k16.row.col.f32.bf16.bf16.f32 " \
                 "{%0,%1,%2,%3}, {%4,%5,%6,%7}, {%8,%9}, {%0,%1,%2,%3};" \
                 : "+f"((d)[0]), "+f"((d)[1]), "+f"((d)[2]), "+f"((d)[3]) \
                 : "r"((a)[0]), "r"((a)[1]), "r"((a)[2]), "r"((a)[3]), \
                   "r"((b)[0]), "r"((b)[1]))

__device__ __forceinline__ float ex2f(float x) {
    float r;
    asm("ex2.approx.ftz.f32 %0, %1;" : "=f"(r) : "f"(x));
    return r;
}

__device__ __forceinline__ uint32_t packbf(float a, float b) {
    __nv_bfloat162 t = __floats2bfloat162_rn(a, b);   // .x = a (low half)
    return *(uint32_t*)&t;
}

// gemm smem swizzle (64B rows, 4x 16B chunks)
__device__ __forceinline__ uint32_t swz(int r, int c) {
    return (uint32_t)(r * 64 + ((c ^ ((r >> 1) & 3)) << 4));
}
// 256B rows, 16x 16B chunks
__device__ __forceinline__ uint32_t swzq(int r, int c) {
    return (uint32_t)(r * 256 + ((c ^ (r & 7)) << 4));
}
// 128B rows, 8x 16B chunks
__device__ __forceinline__ uint32_t swzv(int r, int c) {
    return (uint32_t)(r * 128 + ((c ^ (r & 7)) << 4));
}

__device__ __forceinline__ void split1(float x, __nv_bfloat16& h, __nv_bfloat16& l) {
    h = __float2bfloat16(x);
    l = __float2bfloat16(x - __bfloat162float(h));
}

// ---------------------------------------------------------------------------
// Split fp32 -> (bf16 hi, bf16 lo), flat
// ---------------------------------------------------------------------------
__global__ void split_bf16(const float4* __restrict__ in,
                           uint2* __restrict__ hi, uint2* __restrict__ lo, int n4)
{
    int i = blockIdx.x * blockDim.x + threadIdx.x;
    if (i >= n4) return;
    float4 v = in[i];
    __nv_bfloat16 h0, h1, h2, h3, l0, l1, l2, l3;
    split1(v.x, h0, l0); split1(v.y, h1, l1);
    split1(v.z, h2, l2); split1(v.w, h3, l3);
    uint2 hv, lv;
    hv.x = (uint32_t)__bfloat16_as_ushort(h0) | ((uint32_t)__bfloat16_as_ushort(h1) << 16);
    hv.y = (uint32_t)__bfloat16_as_ushort(h2) | ((uint32_t)__bfloat16_as_ushort(h3) << 16);
    lv.x = (uint32_t)__bfloat16_as_ushort(l0) | ((uint32_t)__bfloat16_as_ushort(l1) << 16);
    lv.y = (uint32_t)__bfloat16_as_ushort(l2) | ((uint32_t)__bfloat16_as_ushort(l3) << 16);
    hi[i] = hv;
    lo[i] = lv;
}

// ---------------------------------------------------------------------------
// mma.sync GEMM (unchanged from round 5): C = Ahi*Bhi^T + Ahi*Blo^T + Alo*Bhi^T
// ---------------------------------------------------------------------------
#define MT_TILE   8192
#define MT_STAGE  32768
#define MT_SMEM   (2 * MT_STAGE)

__device__ __forceinline__ void mt_stage_load(
    const __nv_bfloat16* __restrict__ Ahi, const __nv_bfloat16* __restrict__ Alo,
    const __nv_bfloat16* __restrict__ Bhi, const __nv_bfloat16* __restrict__ Blo,
    int m0, int n0, int K, int k0, uint32_t sstage, int tid)
{
    #pragma unroll
    for (int it = 0; it < 8; it++) {
        int idx = tid + it * 256;
        int t   = idx >> 9;
        int rem = idx & 511;
        int r   = rem >> 2;
        int c   = rem & 3;
        const __nv_bfloat16* base = (t == 0) ? Ahi : (t == 1) ? Alo
                                  : (t == 2) ? Bhi : Blo;
        int row0 = (t < 2) ? m0 : n0;
        const char* src = (const char*)(base + (size_t)(row0 + r) * K + k0) + c * 16;
        uint32_t dst = sstage + (uint32_t)t * MT_TILE + swz(r, c);
        CP_ASYNC16(dst, src);
    }
}

__global__ __launch_bounds__(256)
void gemm_mma(const __nv_bfloat16* __restrict__ Ahi, const __nv_bfloat16* __restrict__ Alo,
              const __nv_bfloat16* __restrict__ Bhi, const __nv_bfloat16* __restrict__ Blo,
              const float* __restrict__ bias, float* __restrict__ C,
              int M, int N, int K)
{
    extern __shared__ char smg[];
    uint32_t sb = s2u(smg);
    int tid = threadIdx.x;
    int wid = tid >> 5, lane = tid & 31;
    int wm = wid & 3, wn = wid >> 2;
    int mbase = wm * 32, nbase = wn * 64;
    int m0 = blockIdx.y * 128, n0 = blockIdx.x * 128;

    float acc[2][8][4];
    #pragma unroll
    for (int i = 0; i < 2; i++)
        #pragma unroll
        for (int j = 0; j < 8; j++)
            #pragma unroll
            for (int q = 0; q < 4; q++) acc[i][j][q] = 0.f;

    const int nkt = K >> 5;

    mt_stage_load(Ahi, Alo, Bhi, Blo, m0, n0, K, 0, sb, tid);
    CP_COMMIT();

    int lrow = lane & 15;
    int lsel = lane >> 4;

    for (int kt = 0; kt < nkt; kt++) {
        uint32_t sbuf = sb + (uint32_t)(kt & 1) * MT_STAGE;
        if (kt + 1 < nkt) {
            mt_stage_load(Ahi, Alo, Bhi, Blo, m0, n0, K, (kt + 1) << 5,
                          sb + (uint32_t)((kt + 1) & 1) * MT_STAGE, tid);
            CP_COMMIT();
            CP_WAIT1();
        } else {
            CP_WAIT0();
        }
        __syncthreads();

        #pragma unroll
        for (int ks = 0; ks < 2; ks++) {
            int kc = ks * 2;
            uint32_t ah[2][4], al[2][4], bh[8][2], bl[8][2];
            #pragma unroll
            for (int f = 0; f < 2; f++) {
                int r = mbase + f * 16 + lrow;
                int c = kc + lsel;
                LDSM4(ah[f][0], ah[f][1], ah[f][2], ah[f][3], sbuf + swz(r, c));
                LDSM4(al[f][0], al[f][1], al[f][2], al[f][3],
                      sbuf + MT_TILE + swz(r, c));
            }
            #pragma unroll
            for (int g = 0; g < 4; g++) {
                int r = nbase + g * 16 + lrow;
                int c = kc + lsel;
                uint32_t r0, r1, r2, r3;
                LDSM4(r0, r1, r2, r3, sbuf + 2 * MT_TILE + swz(r, c));
                bh[2*g][0] = r0; bh[2*g][1] = r2;
                bh[2*g+1][0] = r1; bh[2*g+1][1] = r3;
                LDSM4(r0, r1, r2, r3, sbuf + 3 * MT_TILE + swz(r, c));
                bl[2*g][0] = r0; bl[2*g][1] = r2;
                bl[2*g+1][0] = r1; bl[2*g+1][1] = r3;
            }
            #pragma unroll
            for (int mi = 0; mi < 2; mi++)
                #pragma unroll
                for (int nj = 0; nj < 8; nj++) {
                    MMA16816(acc[mi][nj], ah[mi], bh[nj]);
                    MMA16816(acc[mi][nj], ah[mi], bl[nj]);
                    MMA16816(acc[mi][nj], al[mi], bh[nj]);
                }
        }
        __syncthreads();
    }

    int erow = lane >> 2;
    int ecol = (lane & 3) * 2;
    #pragma unroll
    for (int mi = 0; mi < 2; mi++) {
        #pragma unroll
        for (int nj = 0; nj < 8; nj++) {
            int col = n0 + nbase + nj * 8 + ecol;
            float b0 = bias ? bias[col]     : 0.f;
            float b1 = bias ? bias[col + 1] : 0.f;
            int r0 = m0 + mbase + mi * 16 + erow;
            float2 v0 = make_float2(acc[mi][nj][0] + b0, acc[mi][nj][1] + b1);
            float2 v1 = make_float2(acc[mi][nj][2] + b0, acc[mi][nj][3] + b1);
            *(float2*)(C + (size_t)r0 * N + col)       = v0;
            *(float2*)(C + (size_t)(r0 + 8) * N + col) = v1;
        }
    }
}

// ---------------------------------------------------------------------------
// Copy input kv caches to output regions
// ---------------------------------------------------------------------------
__global__ void copy_cache(const float4* __restrict__ k_in, const float4* __restrict__ v_in,
                           float4* __restrict__ k_out, float4* __restrict__ v_out, int n4)
{
    int i = blockIdx.x * blockDim.x + threadIdx.x;
    if (i < n4) { k_out[i] = k_in[i]; v_out[i] = v_in[i]; }
}

// ---------------------------------------------------------------------------
// RoPE in place on q,k of qkv, then scatter k,v into caches. One block/token.
// ---------------------------------------------------------------------------
__global__ void rope_scatter(float* __restrict__ qkv, const float* __restrict__ cosp,
                             const float* __restrict__ sinp, const int* __restrict__ slot_mapping,
                             float* __restrict__ kc, float* __restrict__ vc)
{
    int row = blockIdx.x;
    int tid = threadIdx.x;
    const float* c = cosp + (size_t)row * D_;
    const float* s = sinp + (size_t)row * D_;
    float* base = qkv + (size_t)row * QKV_N;

    for (int i = tid; i < 14 * 64; i += blockDim.x) {
        int hh = i >> 6, d = i & 63;
        float* p = base + hh * D_;
        float x1 = p[d], x2 = p[d + 64];
        float c1 = c[d], s1 = s[d];
        float c2 = c[d + 64], s2 = s[d + 64];
        p[d]      = x1 * c1 - x2 * s1;
        p[d + 64] = x2 * c2 + x1 * s2;
    }
    __syncthreads();
    int slot = slot_mapping[row];
    for (int i = tid; i < HKV_ * D_; i += blockDim.x) {
        kc[(size_t)slot * (HKV_*D_) + i] = base[H_*D_ + i];
        vc[(size_t)slot * (HKV_*D_) + i] = base[H_*D_ + HKV_*D_ + i];
    }
}

// ---------------------------------------------------------------------------
// Q split: scale by 1/sqrt(D)*log2(e), split hi/lo, relayout to [b][h][s][d]
// ---------------------------------------------------------------------------
__global__ void qsplit(const float* __restrict__ qkv,
                       __nv_bfloat16* __restrict__ qhi, __nv_bfloat16* __restrict__ qlo)
{
    int idx = blockIdx.x * blockDim.x + threadIdx.x;   // float4 idx over q area
    if (idx >= NTOK * 384) return;
    int t = idx / 384;
    int r = idx - t * 384;
    int h = r >> 5, d4 = r & 31;
    int b = t >> 11, s = t & 2047;
    const float qs = 0.08838834764831845f * 1.4426950408889634f;  // scale * log2(e)
    float4 v = *(const float4*)(qkv + (size_t)t * QKV_N + h * D_ + d4 * 4);
    v.x *= qs; v.y *= qs; v.z *= qs; v.w *= qs;
    __nv_bfloat16 h0,h1,h2,h3,l0,l1,l2,l3;
    split1(v.x,h0,l0); split1(v.y,h1,l1); split1(v.z,h2,l2); split1(v.w,h3,l3);
    uint2 hv, lv;
    hv.x = (uint32_t)__bfloat16_as_ushort(h0) | ((uint32_t)__bfloat16_as_ushort(h1) << 16);
    hv.y = (uint32_t)__bfloat16_as_ushort(h2) | ((uint32_t)__bfloat16_as_ushort(h3) << 16);
    lv.x = (uint32_t)__bfloat16_as_ushort(l0) | ((uint32_t)__bfloat16_as_ushort(l1) << 16);
    lv.y = (uint32_t)__bfloat16_as_ushort(l2) | ((uint32_t)__bfloat16_as_ushort(l3) << 16);
    size_t o = ((size_t)(b * H_ + h) * S_ + s) * D_ + d4 * 4;
    *(uint2*)(qhi + o) = hv;
    *(uint2*)(qlo + o) = lv;
}

// ---------------------------------------------------------------------------
// KV split: K -> [b][kvh][s][d] hi/lo; V -> transposed [b][kvh][d][s] hi/lo.
// One block per (b, kvh, 64-row s-tile).
// ---------------------------------------------------------------------------
__global__ __launch_bounds__(256)
void kvsplit(const float* __restrict__ qkv,
             __nv_bfloat16* __restrict__ khi, __nv_bfloat16* __restrict__ klo,
             __nv_bfloat16* __restrict__ vhi, __nv_bfloat16* __restrict__ vlo)
{
    __shared__ float vbuf[64][132];
    int blk = blockIdx.x;
    int st64 = blk & 31;
    int kvh  = (blk >> 5) & 1;
    int b    = blk >> 6;
    int s0 = st64 * 64;
    int tid = threadIdx.x;

    #pragma unroll
    for (int it = 0; it < 8; it++) {
        int idx = tid + it * 256;         // 0..2047
        int r = idx >> 5, c4 = idx & 31;
        const float* rowp = qkv + (size_t)(b * S_ + s0 + r) * QKV_N;
        float4 kv4 = *(const float4*)(rowp + H_*D_ + kvh * D_ + c4 * 4);
        __nv_bfloat16 h0,h1,h2,h3,l0,l1,l2,l3;
        split1(kv4.x,h0,l0); split1(kv4.y,h1,l1); split1(kv4.z,h2,l2); split1(kv4.w,h3,l3);
        uint2 hv, lv;
        hv.x = (uint32_t)__bfloat16_as_ushort(h0) | ((uint32_t)__bfloat16_as_ushort(h1) << 16);
        hv.y = (uint32_t)__bfloat16_as_ushort(h2) | ((uint32_t)__bfloat16_as_ushort(h3) << 16);
        lv.x = (uint32_t)__bfloat16_as_ushort(l0) | ((uint32_t)__bfloat16_as_ushort(l1) << 16);
        lv.y = (uint32_t)__bfloat16_as_ushort(l2) | ((uint32_t)__bfloat16_as_ushort(l3) << 16);
        size_t ko = ((size_t)(b * HKV_ + kvh) * S_ + s0 + r) * D_ + c4 * 4;
        *(uint2*)(khi + ko) = hv;
        *(uint2*)(klo + ko) = lv;

        float4 vv = *(const float4*)(rowp + H_*D_ + HKV_*D_ + kvh * D_ + c4 * 4);
        vbuf[r][c4*4+0] = vv.x; vbuf[r][c4*4+1] = vv.y;
        vbuf[r][c4*4+2] = vv.z; vbuf[r][c4*4+3] = vv.w;
    }
    __syncthreads();

    // transposed write: thread -> (d = tid>>1, s-half = tid&1)
    int d = tid >> 1, half = tid & 1;
    uint32_t hw[16], lw[16];
    #pragma unroll
    for (int j = 0; j < 16; j++) {
        float x0 = vbuf[half*32 + 2*j    ][d];
        float x1 = vbuf[half*32 + 2*j + 1][d];
        __nv_bfloat16 ha, hb, la, lb;
        split1(x0, ha, la); split1(x1, hb, lb);
        hw[j] = (uint32_t)__bfloat16_as_ushort(ha) | ((uint32_t)__bfloat16_as_ushort(hb) << 16);
        lw[j] = (uint32_t)__bfloat16_as_ushort(la) | ((uint32_t)__bfloat16_as_ushort(lb) << 16);
    }
    size_t o = ((size_t)(b * HKV_ + kvh) * D_ + d) * S_ + s0 + half * 32;
    #pragma unroll
    for (int q = 0; q < 4; q++) {
        *(uint4*)(vhi + o + q * 8) = *(uint4*)&hw[q * 4];
        *(uint4*)(vlo + o + q * 8) = *(uint4*)&lw[q * 4];
    }
}

// ---------------------------------------------------------------------------
// Tensor-core flash attention. BLOCK_M=128 (8 warps x m16), BLOCK_N=64, D=128.
// Q hi/lo resident in smem; K/V hi/lo double-buffered via cp.async.
// QK and PV both 3-MMA compensated bf16, fp32 accumulate, exp2-domain softmax.
// ---------------------------------------------------------------------------
#define A2_QBYTES 65536                     // Qhi 32KB + Qlo 32KB
#define A2_STAGE  65536                     // Khi/Klo 16+16KB, Vhi/Vlo 16+16KB
#define A2_SMEM   (A2_QBYTES + 2 * A2_STAGE)  // 196608

__global__ __launch_bounds__(256, 1)
void attn2(const __nv_bfloat16* __restrict__ qhi, const __nv_bfloat16* __restrict__ qlo,
           const __nv_bfloat16* __restrict__ khi, const __nv_bfloat16* __restrict__ klo,
           const __nv_bfloat16* __restrict__ vhi, const __nv_bfloat16* __restrict__ vlo,
           float* __restrict__ ao)
{
    extern __shared__ char sm2[];
    uint32_t sb = s2u(sm2);
    int qt = blockIdx.x, h = blockIdx.y, b = blockIdx.z;
    int kvh = h / NGROUPS_;
    int q0 = qt * 128;
    int tid = threadIdx.x, wid = tid >> 5, lane = tid & 31;
    int lrow = lane & 15, lsel = lane >> 4;

    const char* qh_base = (const char*)(qhi + ((size_t)(b * H_ + h) * S_ + q0) * D_);
    const char* ql_base = (const char*)(qlo + ((size_t)(b * H_ + h) * S_ + q0) * D_);
    const char* kh_base = (const char*)(khi + ((size_t)(b * HKV_ + kvh) * S_) * D_);
    const char* kl_base = (const char*)(klo + ((size_t)(b * HKV_ + kvh) * S_) * D_);
    const char* vh_base = (const char*)(vhi + ((size_t)(b * HKV_ + kvh) * D_) * S_);
    const char* vl_base = (const char*)(vlo + ((size_t)(b * HKV_ + kvh) * D_) * S_);

    // Q tile loads (once)
    #pragma unroll
    for (int it = 0; it < 8; it++) {
        int idx = tid + it * 256;          // 0..2047
        int r = idx >> 4, c = idx & 15;
        CP_ASYNC16(sb + swzq(r, c),          qh_base + r * 256 + c * 16);
        CP_ASYNC16(sb + 32768 + swzq(r, c),  ql_base + r * 256 + c * 16);
    }

    const int nt = 2 * qt + 2;

    // stage loader
    auto load_kv = [&](int t, int st_i) {
        uint32_t st = sb + A2_QBYTES + (uint32_t)st_i * A2_STAGE;
        int k0 = t * 64;
        #pragma unroll
        for (int it = 0; it < 4; it++) {
            int idx = tid + it * 256;      // 0..1023
            int r = idx >> 4, c = idx & 15;
            CP_ASYNC16(st + swzq(r, c),          kh_base + (size_t)(k0 + r) * 256 + c * 16);
            CP_ASYNC16(st + 16384 + swzq(r, c),  kl_base + (size_t)(k0 + r) * 256 + c * 16);
        }
        #pragma unroll
        for (int it = 0; it < 4; it++) {
            int idx = tid + it * 256;      // 0..1023
            int r = idx >> 3, c = idx & 7;
            CP_ASYNC16(st + 32768 + swzv(r, c),
                       vh_base + (size_t)r * (S_ * 2) + k0 * 2 + c * 16);
            CP_ASYNC16(st + 49152 + swzv(r, c),
                       vl_base + (size_t)r * (S_ * 2) + k0 * 2 + c * 16);
        }
    };

    load_kv(0, 0);
    CP_COMMIT();   // group contains Q + stage0

    float oacc[16][4];
    #pragma unroll
    for (int i = 0; i < 16; i++)
        #pragma unroll
        for (int j = 0; j < 4; j++) oacc[i][j] = 0.f;
    float m0 = -1e30f, m1 = -1e30f, l0 = 0.f, l1 = 0.f;

    for (int t = 0; t < nt; t++) {
        uint32_t st = sb + A2_QBYTES + (uint32_t)(t & 1) * A2_STAGE;
        if (t + 1 < nt) {
            load_kv(t + 1, (t + 1) & 1);
            CP_COMMIT();
            CP_WAIT1();
        } else {
            CP_WAIT0();
        }
        __syncthreads();

        // ---- scores S = Q K^T (compensated) ----
        float sacc[8][4];
        #pragma unroll
        for (int i = 0; i < 8; i++)
            #pragma unroll
            for (int j = 0; j < 4; j++) sacc[i][j] = 0.f;

        #pragma unroll
        for (int kc = 0; kc < 8; kc++) {
            uint32_t qa[4], qla[4];
            LDSM4(qa[0], qa[1], qa[2], qa[3],
                  sb + swzq(wid * 16 + lrow, kc * 2 + lsel));
            LDSM4(qla[0], qla[1], qla[2], qla[3],
                  sb + 32768 + swzq(wid * 16 + lrow, kc * 2 + lsel));
            uint32_t bh[8][2], bl[8][2];
            #pragma unroll
            for (int g = 0; g < 4; g++) {
                uint32_t r0, r1, r2, r3;
                LDSM4(r0, r1, r2, r3, st + swzq(g * 16 + lrow, kc * 2 + lsel));
                bh[2*g][0] = r0; bh[2*g][1] = r2;
                bh[2*g+1][0] = r1; bh[2*g+1][1] = r3;
                LDSM4(r0, r1, r2, r3, st + 16384 + swzq(g * 16 + lrow, kc * 2 + lsel));
                bl[2*g][0] = r0; bl[2*g][1] = r2;
                bl[2*g+1][0] = r1; bl[2*g+1][1] = r3;
            }
            #pragma unroll
            for (int nj = 0; nj < 8; nj++) {
                MMA16816(sacc[nj], qa, bh[nj]);
                MMA16816(sacc[nj], qa, bl[nj]);
                MMA16816(sacc[nj], qla, bh[nj]);
            }
        }

        // ---- causal mask (last two tiles only) ----
        int k0 = t * 64;
        if (t >= nt - 2) {
            int qr0 = q0 + wid * 16 + (lane >> 2);
            int qr1 = qr0 + 8;
            #pragma unroll
            for (int nj = 0; nj < 8; nj++) {
                int kcol = k0 + nj * 8 + (lane & 3) * 2;
                if (kcol     > qr0) sacc[nj][0] = -1e30f;
                if (kcol + 1 > qr0) sacc[nj][1] = -1e30f;
                if (kcol     > qr1) sacc[nj][2] = -1e30f;
                if (kcol + 1 > qr1) sacc[nj][3] = -1e30f;
            }
        }

        // ---- online softmax (log2 domain; Q pre-scaled) ----
        float mx0 = -1e30f, mx1 = -1e30f;
        #pragma unroll
        for (int nj = 0; nj < 8; nj++) {
            mx0 = fmaxf(mx0, fmaxf(sacc[nj][0], sacc[nj][1]));
            mx1 = fmaxf(mx1, fmaxf(sacc[nj][2], sacc[nj][3]));
        }
        mx0 = fmaxf(mx0, __shfl_xor_sync(0xffffffffu, mx0, 1));
        mx0 = fmaxf(mx0, __shfl_xor_sync(0xffffffffu, mx0, 2));
        mx1 = fmaxf(mx1, __shfl_xor_sync(0xffffffffu, mx1, 1));
        mx1 = fmaxf(mx1, __shfl_xor_sync(0xffffffffu, mx1, 2));
        float nm0 = fmaxf(m0, mx0), nm1 = fmaxf(m1, mx1);
        float f0 = ex2f(m0 - nm0), f1 = ex2f(m1 - nm1);
        m0 = nm0; m1 = nm1;

        uint32_t ph[4][4], pl[4][4];
        float rs0 = 0.f, rs1 = 0.f;
        #pragma unroll
        for (int j = 0; j < 4; j++) {
            float pe0 = ex2f(sacc[2*j][0] - nm0);
            float pe1 = ex2f(sacc[2*j][1] - nm0);
            float pe2 = ex2f(sacc[2*j][2] - nm1);
            float pe3 = ex2f(sacc[2*j][3] - nm1);
            float po0 = ex2f(sacc[2*j+1][0] - nm0);
            float po1 = ex2f(sacc[2*j+1][1] - nm0);
            float po2 = ex2f(sacc[2*j+1][2] - nm1);
            float po3 = ex2f(sacc[2*j+1][3] - nm1);
            rs0 += pe0 + pe1 + po0 + po1;
            rs1 += pe2 + pe3 + po2 + po3;
            __nv_bfloat16 hh, ll;
            float r;
            // hi packs
            ph[j][0] = packbf(pe0, pe1);
            ph[j][1] = packbf(pe2, pe3);
            ph[j][2] = packbf(po0, po1);
            ph[j][3] = packbf(po2, po3);
            // lo packs (residuals)
            hh = __float2bfloat16(pe0); r = pe0 - __bfloat162float(hh); float q0r = r;
            hh = __float2bfloat16(pe1); r = pe1 - __bfloat162float(hh);
            pl[j][0] = packbf(q0r, r);
            hh = __float2bfloat16(pe2); r = pe2 - __bfloat162float(hh); q0r = r;
            hh = __float2bfloat16(pe3); r = pe3 - __bfloat162float(hh);
            pl[j][1] = packbf(q0r, r);
            hh = __float2bfloat16(po0); r = po0 - __bfloat162float(hh); q0r = r;
            hh = __float2bfloat16(po1); r = po1 - __bfloat162float(hh);
            pl[j][2] = packbf(q0r, r);
            hh = __float2bfloat16(po2); r = po2 - __bfloat162float(hh); q0r = r;
            hh = __float2bfloat16(po3); r = po3 - __bfloat162float(hh);
            pl[j][3] = packbf(q0r, r);
            (void)ll;
        }
        rs0 += __shfl_xor_sync(0xffffffffu, rs0, 1);
        rs0 += __shfl_xor_sync(0xffffffffu, rs0, 2);
        rs1 += __shfl_xor_sync(0xffffffffu, rs1, 1);
        rs1 += __shfl_xor_sync(0xffffffffu, rs1, 2);
        l0 = l0 * f0 + rs0;
        l1 = l1 * f1 + rs1;
        #pragma unroll
        for (int nj = 0; nj < 16; nj++) {
            oacc[nj][0] *= f0; oacc[nj][1] *= f0;
            oacc[nj][2] *= f1; oacc[nj][3] *= f1;
        }

        // ---- O += P V (compensated) ----
        #pragma unroll
        for (int j = 0; j < 4; j++) {
            #pragma unroll
            for (int g = 0; g < 8; g++) {
                uint32_t r0, r1, r2, r3, s0r, s1r, s2r, s3r;
                LDSM4(r0, r1, r2, r3, st + 32768 + swzv(g * 16 + lrow, j * 2 + lsel));
                LDSM4(s0r, s1r, s2r, s3r, st + 49152 + swzv(g * 16 + lrow, j * 2 + lsel));
                uint32_t vh0[2] = {r0, r2}, vh1[2] = {r1, r3};
                uint32_t vl0[2] = {s0r, s2r}, vl1[2] = {s1r, s3r};
                MMA16816(oacc[2*g],   ph[j], vh0);
                MMA16816(oacc[2*g],   ph[j], vl0);
                MMA16816(oacc[2*g],   pl[j], vh0);
                MMA16816(oacc[2*g+1], ph[j], vh1);
                MMA16816(oacc[2*g+1], ph[j], vl1);
                MMA16816(oacc[2*g+1], pl[j], vh1);
            }
        }
        __syncthreads();
    }

    // ---- epilogue ----
    float inv0 = 1.f / l0, inv1 = 1.f / l1;
    int r0g = q0 + wid * 16 + (lane >> 2);
    #pragma unroll
    for (int nj = 0; nj < 16; nj++) {
        int d = nj * 8 + (lane & 3) * 2;
        float2 v0 = make_float2(oacc[nj][0] * inv0, oacc[nj][1] * inv0);
        float2 v1 = make_float2(oacc[nj][2] * inv1, oacc[nj][3] * inv1);
        *(float2*)(ao + ((size_t)(b * S_ + r0g)) * HID_ + h * D_ + d)     = v0;
        *(float2*)(ao + ((size_t)(b * S_ + r0g + 8)) * HID_ + h * D_ + d) = v1;
    }
}

// ---------------------------------------------------------------------------
extern "C" void kernel_launch(void* const* d_in, const int* in_sizes, int n_in,
                              void* d_out, int out_size)
{
    const float* x     = (const float*)d_in[0];
    const float* cosp  = (const float*)d_in[1];
    const float* sinp  = (const float*)d_in[2];
    const float* kci   = (const float*)d_in[3];
    const float* vci   = (const float*)d_in[4];
    const int*   slot  = (const int*)  d_in[5];
    const float* Wqkv  = (const float*)d_in[6];
    const float* bqkv  = (const float*)d_in[7];
    const float* Wo    = (const float*)d_in[8];

    float* out = (float*)d_out;
    float* kc  = out + (size_t)NTOK * HID_;
    float* vc  = kc  + (size_t)NSLOTS_ * HKV_ * D_;

    float* qkv; cudaGetSymbolAddress((void**)&qkv, g_qkv);
    float* ao;  cudaGetSymbolAddress((void**)&ao,  g_ao);
    __nv_bfloat16 *xhi, *xlo, *wqhi, *wqlo, *wohi, *wolo, *aohi, *aolo;
    __nv_bfloat16 *qhi, *qlo, *khi, *klo, *vhi, *vlo;
    cudaGetSymbolAddress((void**)&xhi,  g_xhi);
    cudaGetSymbolAddress((void**)&xlo,  g_xlo);
    cudaGetSymbolAddress((void**)&wqhi, g_wqhi);
    cudaGetSymbolAddress((void**)&wqlo, g_wqlo);
    cudaGetSymbolAddress((void**)&wohi, g_wohi);
    cudaGetSymbolAddress((void**)&wolo, g_wolo);
    cudaGetSymbolAddress((void**)&aohi, g_aohi);
    cudaGetSymbolAddress((void**)&aolo, g_aolo);
    cudaGetSymbolAddress((void**)&qhi,  g_qhi);
    cudaGetSymbolAddress((void**)&qlo,  g_qlo);
    cudaGetSymbolAddress((void**)&khi,  g_khi);
    cudaGetSymbolAddress((void**)&klo,  g_klo);
    cudaGetSymbolAddress((void**)&vhi,  g_vhi);
    cudaGetSymbolAddress((void**)&vlo,  g_vlo);

    cudaFuncSetAttribute(gemm_mma, cudaFuncAttributeMaxDynamicSharedMemorySize, MT_SMEM);
    cudaFuncSetAttribute(attn2, cudaFuncAttributeMaxDynamicSharedMemorySize, A2_SMEM);

    // 0) fp32 -> bf16 hi/lo splits for GEMM operands
    {
        int n4 = NTOK * HID_ / 4;
        split_bf16<<<(n4 + 255) / 256, 256>>>((const float4*)x, (uint2*)xhi, (uint2*)xlo, n4);
        n4 = QKV_N * HID_ / 4;
        split_bf16<<<(n4 + 255) / 256, 256>>>((const float4*)Wqkv, (uint2*)wqhi, (uint2*)wqlo, n4);
        n4 = HID_ * HID_ / 4;
        split_bf16<<<(n4 + 255) / 256, 256>>>((const float4*)Wo, (uint2*)wohi, (uint2*)wolo, n4);
    }

    // 1) QKV projection (tensor cores)
    gemm_mma<<<dim3(QKV_N / 128, NTOK / 128), 256, MT_SMEM>>>(
        xhi, xlo, wqhi, wqlo, bqkv, qkv, NTOK, QKV_N, HID_);

    // 2) Copy input caches to output
    {
        int n4 = NSLOTS_ * HKV_ * D_ / 4;
        copy_cache<<<(n4 + 255) / 256, 256>>>((const float4*)kci, (const float4*)vci,
                                              (float4*)kc, (float4*)vc, n4);
    }

    // 3) RoPE + scatter
    rope_scatter<<<NTOK, 256>>>(qkv, cosp, sinp, slot, kc, vc);

    // 4) Split Q/K/V (post-RoPE) into hi/lo bf16 attention layouts
    {
        int n = NTOK * 384;
        qsplit<<<(n + 255) / 256, 256>>>(qkv, qhi, qlo);
        kvsplit<<<B_ * HKV_ * (S_ / 64), 256>>>(qkv, khi, klo, vhi, vlo);
    }

    // 5) Tensor-core flash attention
    attn2<<<dim3(S_ / 128, H_, B_), 256, A2_SMEM>>>(qhi, qlo, khi, klo, vhi, vlo, ao);

    // 6) Split attention output, then out projection (tensor cores)
    {
        int n4 = NTOK * HID_ / 4;
        split_bf16<<<(n4 + 255) / 256, 256>>>((const float4*)ao, (uint2*)aohi, (uint2*)aolo, n4);
    }
    gemm_mma<<<dim3(HID_ / 128, NTOK / 128), 256, MT_SMEM>>>(
        aohi, aolo, wohi, wolo, nullptr, out, NTOK, HID_, HID_);
}

// round 9
// speedup vs baseline: 3.0917x; 1.0204x over previous
#include <cuda_runtime.h>
#include <cuda_bf16.h>
#include <math.h>
#include <stdint.h>

// Problem constants
#define B_    4
#define S_    2048
#define HID_  1536
#define H_    12
#define HKV_  2
#define D_    128
#define NGROUPS_ 6
#define NSLOTS_ 16384
#define NTOK  (B_ * S_)            // 8192
#define QKV_N (H_*D_ + 2*HKV_*D_)  // 2048

// Scratch (device globals; allocation in kernel_launch is forbidden)
__device__ float g_qkv[(size_t)NTOK * QKV_N];   // 64 MB
__device__ __nv_bfloat16 g_xhi [(size_t)NTOK * HID_];
__device__ __nv_bfloat16 g_xlo [(size_t)NTOK * HID_];
__device__ __nv_bfloat16 g_wqhi[(size_t)QKV_N * HID_];
__device__ __nv_bfloat16 g_wqlo[(size_t)QKV_N * HID_];
__device__ __nv_bfloat16 g_wohi[(size_t)HID_ * HID_];
__device__ __nv_bfloat16 g_wolo[(size_t)HID_ * HID_];
__device__ __nv_bfloat16 g_aohi[(size_t)NTOK * HID_];
__device__ __nv_bfloat16 g_aolo[(size_t)NTOK * HID_];
// Attention operand buffers (hi/lo splits)
__device__ __nv_bfloat16 g_qhi[(size_t)B_ * H_ * S_ * D_];
__device__ __nv_bfloat16 g_qlo[(size_t)B_ * H_ * S_ * D_];
__device__ __nv_bfloat16 g_khi[(size_t)B_ * HKV_ * S_ * D_];
__device__ __nv_bfloat16 g_klo[(size_t)B_ * HKV_ * S_ * D_];
__device__ __nv_bfloat16 g_vhi[(size_t)B_ * HKV_ * D_ * S_];  // transposed [d][s]
__device__ __nv_bfloat16 g_vlo[(size_t)B_ * HKV_ * D_ * S_];

// ---------------------------------------------------------------------------
// Portable PTX helpers
// ---------------------------------------------------------------------------
__device__ __forceinline__ uint32_t s2u(const void* p) {
    uint32_t a;
    asm("{ .reg .u64 t; cvta.to.shared.u64 t, %1; cvt.u32.u64 %0, t; }"
        : "=r"(a) : "l"(p));
    return a;
}

#define CP_ASYNC16(dst, src) \
    asm volatile("cp.async.cg.shared.global [%0], [%1], 16;" \
                 :: "r"(dst), "l"(src))
#define CP_COMMIT() asm volatile("cp.async.commit_group;")
#define CP_WAIT1()  asm volatile("cp.async.wait_group 1;")
#define CP_WAIT0()  asm volatile("cp.async.wait_group 0;")

#define LDSM4(r0, r1, r2, r3, addr) \
    asm volatile("ldmatrix.sync.aligned.m8n8.x4.shared.b16 {%0,%1,%2,%3}, [%4];" \
                 : "=r"(r0), "=r"(r1), "=r"(r2), "=r"(r3) : "r"(addr))

#define MMA16816(d, a, b) \
    asm volatile("mma.sync.aligned.m16n8k16.row.col.f32.bf16.bf16.f32 " \
                 "{%0,%1,%2,%3}, {%4,%5,%6,%7}, {%8,%9}, {%0,%1,%2,%3};" \
                 : "+f"((d)[0]), "+f"((d)[1]), "+f"((d)[2]), "+f"((d)[3]) \
                 : "r"((a)[0]), "r"((a)[1]), "r"((a)[2]), "r"((a)[3]), \
                   "r"((b)[0]), "r"((b)[1]))

__device__ __forceinline__ float ex2f(float x) {
    float r;
    asm("ex2.approx.ftz.f32 %0, %1;" : "=f"(r) : "f"(x));
    return r;
}

__device__ __forceinline__ uint32_t packbf(float a, float b) {
    __nv_bfloat162 t = __floats2bfloat162_rn(a, b);
    return *(uint32_t*)&t;
}

// gemm smem swizzle (64B rows, 4x 16B chunks)
__device__ __forceinline__ uint32_t swz(int r, int c) {
    return (uint32_t)(r * 64 + ((c ^ ((r >> 1) & 3)) << 4));
}
// 256B rows, 16x 16B chunks
__device__ __forceinline__ uint32_t swzq(int r, int c) {
    return (uint32_t)(r * 256 + ((c ^ (r & 7)) << 4));
}
// 128B rows, 8x 16B chunks
__device__ __forceinline__ uint32_t swzv(int r, int c) {
    return (uint32_t)(r * 128 + ((c ^ (r & 7)) << 4));
}

__device__ __forceinline__ void split1(float x, __nv_bfloat16& h, __nv_bfloat16& l) {
    h = __float2bfloat16(x);
    l = __float2bfloat16(x - __bfloat162float(h));
}

__device__ __forceinline__ uint32_t pack2(__nv_bfloat16 a, __nv_bfloat16 b) {
    return (uint32_t)__bfloat16_as_ushort(a) | ((uint32_t)__bfloat16_as_ushort(b) << 16);
}

// ---------------------------------------------------------------------------
// Split fp32 -> (bf16 hi, bf16 lo), flat
// ---------------------------------------------------------------------------
__global__ void split_bf16(const float4* __restrict__ in,
                           uint2* __restrict__ hi, uint2* __restrict__ lo, int n4)
{
    int i = blockIdx.x * blockDim.x + threadIdx.x;
    if (i >= n4) return;
    float4 v = in[i];
    __nv_bfloat16 h0, h1, h2, h3, l0, l1, l2, l3;
    split1(v.x, h0, l0); split1(v.y, h1, l1);
    split1(v.z, h2, l2); split1(v.w, h3, l3);
    uint2 hv, lv;
    hv.x = pack2(h0, h1); hv.y = pack2(h2, h3);
    lv.x = pack2(l0, l1); lv.y = pack2(l2, l3);
    hi[i] = hv;
    lo[i] = lv;
}

// ---------------------------------------------------------------------------
// mma.sync GEMM, 3-stage cp.async pipeline:
// C = Ahi*Bhi^T + Ahi*Blo^T + Alo*Bhi^T (+bias)
// ---------------------------------------------------------------------------
#define MT_TILE   8192
#define MT_STAGE  32768
#define MT_SMEM   (3 * MT_STAGE)   // 96 KB

__device__ __forceinline__ void mt_stage_load(
    const __nv_bfloat16* __restrict__ Ahi, const __nv_bfloat16* __restrict__ Alo,
    const __nv_bfloat16* __restrict__ Bhi, const __nv_bfloat16* __restrict__ Blo,
    int m0, int n0, int K, int k0, uint32_t sstage, int tid)
{
    #pragma unroll
    for (int it = 0; it < 8; it++) {
        int idx = tid + it * 256;
        int t   = idx >> 9;
        int rem = idx & 511;
        int r   = rem >> 2;
        int c   = rem & 3;
        const __nv_bfloat16* base = (t == 0) ? Ahi : (t == 1) ? Alo
                                  : (t == 2) ? Bhi : Blo;
        int row0 = (t < 2) ? m0 : n0;
        const char* src = (const char*)(base + (size_t)(row0 + r) * K + k0) + c * 16;
        uint32_t dst = sstage + (uint32_t)t * MT_TILE + swz(r, c);
        CP_ASYNC16(dst, src);
    }
}

__global__ __launch_bounds__(256)
void gemm_mma(const __nv_bfloat16* __restrict__ Ahi, const __nv_bfloat16* __restrict__ Alo,
              const __nv_bfloat16* __restrict__ Bhi, const __nv_bfloat16* __restrict__ Blo,
              const float* __restrict__ bias, float* __restrict__ C,
              int M, int N, int K)
{
    extern __shared__ char smg[];
    uint32_t sb = s2u(smg);
    int tid = threadIdx.x;
    int wid = tid >> 5, lane = tid & 31;
    int wm = wid & 3, wn = wid >> 2;
    int mbase = wm * 32, nbase = wn * 64;
    int m0 = blockIdx.y * 128, n0 = blockIdx.x * 128;

    float acc[2][8][4];
    #pragma unroll
    for (int i = 0; i < 2; i++)
        #pragma unroll
        for (int j = 0; j < 8; j++)
            #pragma unroll
            for (int q = 0; q < 4; q++) acc[i][j][q] = 0.f;

    const int nkt = K >> 5;

    mt_stage_load(Ahi, Alo, Bhi, Blo, m0, n0, K, 0, sb, tid);
    CP_COMMIT();
    mt_stage_load(Ahi, Alo, Bhi, Blo, m0, n0, K, 32, sb + MT_STAGE, tid);
    CP_COMMIT();

    int lrow = lane & 15;
    int lsel = lane >> 4;

    for (int kt = 0; kt < nkt; kt++) {
        if (kt == nkt - 1) { CP_WAIT0(); } else { CP_WAIT1(); }
        __syncthreads();
        if (kt + 2 < nkt) {
            mt_stage_load(Ahi, Alo, Bhi, Blo, m0, n0, K, (kt + 2) << 5,
                          sb + (uint32_t)((kt + 2) % 3) * MT_STAGE, tid);
            CP_COMMIT();
        }
        uint32_t sbuf = sb + (uint32_t)(kt % 3) * MT_STAGE;

        #pragma unroll
        for (int ks = 0; ks < 2; ks++) {
            int kc = ks * 2;
            uint32_t ah[2][4], al[2][4], bh[8][2], bl[8][2];
            #pragma unroll
            for (int f = 0; f < 2; f++) {
                int r = mbase + f * 16 + lrow;
                int c = kc + lsel;
                LDSM4(ah[f][0], ah[f][1], ah[f][2], ah[f][3], sbuf + swz(r, c));
                LDSM4(al[f][0], al[f][1], al[f][2], al[f][3],
                      sbuf + MT_TILE + swz(r, c));
            }
            #pragma unroll
            for (int g = 0; g < 4; g++) {
                int r = nbase + g * 16 + lrow;
                int c = kc + lsel;
                uint32_t r0, r1, r2, r3;
                LDSM4(r0, r1, r2, r3, sbuf + 2 * MT_TILE + swz(r, c));
                bh[2*g][0] = r0; bh[2*g][1] = r2;
                bh[2*g+1][0] = r1; bh[2*g+1][1] = r3;
                LDSM4(r0, r1, r2, r3, sbuf + 3 * MT_TILE + swz(r, c));
                bl[2*g][0] = r0; bl[2*g][1] = r2;
                bl[2*g+1][0] = r1; bl[2*g+1][1] = r3;
            }
            #pragma unroll
            for (int mi = 0; mi < 2; mi++)
                #pragma unroll
                for (int nj = 0; nj < 8; nj++) {
                    MMA16816(acc[mi][nj], ah[mi], bh[nj]);
                    MMA16816(acc[mi][nj], ah[mi], bl[nj]);
                    MMA16816(acc[mi][nj], al[mi], bh[nj]);
                }
        }
    }

    int erow = lane >> 2;
    int ecol = (lane & 3) * 2;
    #pragma unroll
    for (int mi = 0; mi < 2; mi++) {
        #pragma unroll
        for (int nj = 0; nj < 8; nj++) {
            int col = n0 + nbase + nj * 8 + ecol;
            float b0 = bias ? bias[col]     : 0.f;
            float b1 = bias ? bias[col + 1] : 0.f;
            int r0 = m0 + mbase + mi * 16 + erow;
            float2 v0 = make_float2(acc[mi][nj][0] + b0, acc[mi][nj][1] + b1);
            float2 v1 = make_float2(acc[mi][nj][2] + b0, acc[mi][nj][3] + b1);
            *(float2*)(C + (size_t)r0 * N + col)       = v0;
            *(float2*)(C + (size_t)(r0 + 8) * N + col) = v1;
        }
    }
}

// ---------------------------------------------------------------------------
// Copy input kv caches to output regions
// ---------------------------------------------------------------------------
__global__ void copy_cache(const float4* __restrict__ k_in, const float4* __restrict__ v_in,
                           float4* __restrict__ k_out, float4* __restrict__ v_out, int n4)
{
    int i = blockIdx.x * blockDim.x + threadIdx.x;
    if (i < n4) { k_out[i] = k_in[i]; v_out[i] = v_in[i]; }
}

// ---------------------------------------------------------------------------
// Fused Q RoPE + scale + hi/lo split -> [b][h][s][d]. qkv untouched.
// Thread handles 4 consecutive d in the lower half (pairs with d+64).
// ---------------------------------------------------------------------------
__global__ void qrope(const float* __restrict__ qkv, const float* __restrict__ cosp,
                      const float* __restrict__ sinp,
                      __nv_bfloat16* __restrict__ qhi, __nv_bfloat16* __restrict__ qlo)
{
    int idx = blockIdx.x * blockDim.x + threadIdx.x;
    if (idx >= NTOK * H_ * 16) return;
    int t  = idx / (H_ * 16);
    int r  = idx - t * (H_ * 16);
    int h  = r >> 4, d4 = r & 15;
    int d  = d4 * 4;
    int b  = t >> 11, s = t & 2047;

    const float* rowp = qkv + (size_t)t * QKV_N + h * D_;
    float4 x1 = *(const float4*)(rowp + d);
    float4 x2 = *(const float4*)(rowp + d + 64);
    const float* cp = cosp + (size_t)t * D_;
    const float* sp = sinp + (size_t)t * D_;
    float4 c1 = *(const float4*)(cp + d),      s1 = *(const float4*)(sp + d);
    float4 c2 = *(const float4*)(cp + d + 64), s2 = *(const float4*)(sp + d + 64);

    const float qs = 0.08838834764831845f * 1.4426950408889634f;
    float o1[4], o2[4];
    o1[0] = (x1.x * c1.x - x2.x * s1.x) * qs;
    o1[1] = (x1.y * c1.y - x2.y * s1.y) * qs;
    o1[2] = (x1.z * c1.z - x2.z * s1.z) * qs;
    o1[3] = (x1.w * c1.w - x2.w * s1.w) * qs;
    o2[0] = (x2.x * c2.x + x1.x * s2.x) * qs;
    o2[1] = (x2.y * c2.y + x1.y * s2.y) * qs;
    o2[2] = (x2.z * c2.z + x1.z * s2.z) * qs;
    o2[3] = (x2.w * c2.w + x1.w * s2.w) * qs;

    __nv_bfloat16 hh[4], ll[4];
    uint2 hv, lv;
    size_t o = ((size_t)(b * H_ + h) * S_ + s) * D_;
    #pragma unroll
    for (int j = 0; j < 4; j++) split1(o1[j], hh[j], ll[j]);
    hv.x = pack2(hh[0], hh[1]); hv.y = pack2(hh[2], hh[3]);
    lv.x = pack2(ll[0], ll[1]); lv.y = pack2(ll[2], ll[3]);
    *(uint2*)(qhi + o + d) = hv;
    *(uint2*)(qlo + o + d) = lv;
    #pragma unroll
    for (int j = 0; j < 4; j++) split1(o2[j], hh[j], ll[j]);
    hv.x = pack2(hh[0], hh[1]); hv.y = pack2(hh[2], hh[3]);
    lv.x = pack2(ll[0], ll[1]); lv.y = pack2(ll[2], ll[3]);
    *(uint2*)(qhi + o + d + 64) = hv;
    *(uint2*)(qlo + o + d + 64) = lv;
}

// ---------------------------------------------------------------------------
// Fused KV: K rope + split + cache scatter; V split + transpose + cache scatter.
// One block per (b, kvh, 64-token tile). qkv untouched.
// ---------------------------------------------------------------------------
__global__ __launch_bounds__(256)
void kvrope(const float* __restrict__ qkv, const float* __restrict__ cosp,
            const float* __restrict__ sinp, const int* __restrict__ slot_mapping,
            float* __restrict__ kc, float* __restrict__ vc,
            __nv_bfloat16* __restrict__ khi, __nv_bfloat16* __restrict__ klo,
            __nv_bfloat16* __restrict__ vhi, __nv_bfloat16* __restrict__ vlo)
{
    __shared__ float vbuf[64][132];
    int blk = blockIdx.x;
    int st64 = blk & 31;
    int kvh  = (blk >> 5) & 1;
    int b    = blk >> 6;
    int s0 = st64 * 64;
    int tid = threadIdx.x;

    // ---- K: rope + split + scatter (roped fp32 into cache) ----
    #pragma unroll
    for (int it = 0; it < 4; it++) {
        int idx = tid + it * 256;       // 0..1023
        int r = idx >> 4, d4 = idx & 15;
        int d = d4 * 4;
        int t = b * S_ + s0 + r;
        const float* rowp = qkv + (size_t)t * QKV_N + H_*D_ + kvh * D_;
        float4 x1 = *(const float4*)(rowp + d);
        float4 x2 = *(const float4*)(rowp + d + 64);
        const float* cp = cosp + (size_t)t * D_;
        const float* sp = sinp + (size_t)t * D_;
        float4 c1 = *(const float4*)(cp + d),      s1 = *(const float4*)(sp + d);
        float4 c2 = *(const float4*)(cp + d + 64), s2 = *(const float4*)(sp + d + 64);
        float4 o1, o2;
        o1.x = x1.x * c1.x - x2.x * s1.x;
        o1.y = x1.y * c1.y - x2.y * s1.y;
        o1.z = x1.z * c1.z - x2.z * s1.z;
        o1.w = x1.w * c1.w - x2.w * s1.w;
        o2.x = x2.x * c2.x + x1.x * s2.x;
        o2.y = x2.y * c2.y + x1.y * s2.y;
        o2.z = x2.z * c2.z + x1.z * s2.z;
        o2.w = x2.w * c2.w + x1.w * s2.w;

        int slot = slot_mapping[t];
        float* kcp = kc + (size_t)slot * (HKV_*D_) + kvh * D_;
        *(float4*)(kcp + d)      = o1;
        *(float4*)(kcp + d + 64) = o2;

        __nv_bfloat16 hh[4], ll[4];
        uint2 hv, lv;
        size_t ko = ((size_t)(b * HKV_ + kvh) * S_ + s0 + r) * D_;
        split1(o1.x, hh[0], ll[0]); split1(o1.y, hh[1], ll[1]);
        split1(o1.z, hh[2], ll[2]); split1(o1.w, hh[3], ll[3]);
        hv.x = pack2(hh[0], hh[1]); hv.y = pack2(hh[2], hh[3]);
        lv.x = pack2(ll[0], ll[1]); lv.y = pack2(ll[2], ll[3]);
        *(uint2*)(khi + ko + d) = hv;
        *(uint2*)(klo + ko + d) = lv;
        split1(o2.x, hh[0], ll[0]); split1(o2.y, hh[1], ll[1]);
        split1(o2.z, hh[2], ll[2]); split1(o2.w, hh[3], ll[3]);
        hv.x = pack2(hh[0], hh[1]); hv.y = pack2(hh[2], hh[3]);
        lv.x = pack2(ll[0], ll[1]); lv.y = pack2(ll[2], ll[3]);
        *(uint2*)(khi + ko + d + 64) = hv;
        *(uint2*)(klo + ko + d + 64) = lv;
    }

    // ---- V: load + cache scatter + smem for transpose ----
    #pragma unroll
    for (int it = 0; it < 8; it++) {
        int idx = tid + it * 256;       // 0..2047
        int r = idx >> 5, c4 = idx & 31;
        int t = b * S_ + s0 + r;
        float4 vv = *(const float4*)(qkv + (size_t)t * QKV_N
                                     + H_*D_ + HKV_*D_ + kvh * D_ + c4 * 4);
        int slot = slot_mapping[t];
        *(float4*)(vc + (size_t)slot * (HKV_*D_) + kvh * D_ + c4 * 4) = vv;
        vbuf[r][c4*4+0] = vv.x; vbuf[r][c4*4+1] = vv.y;
        vbuf[r][c4*4+2] = vv.z; vbuf[r][c4*4+3] = vv.w;
    }
    __syncthreads();

    // transposed write: thread -> (d = tid>>1, s-half = tid&1)
    int d = tid >> 1, half = tid & 1;
    uint32_t hw[16], lw[16];
    #pragma unroll
    for (int j = 0; j < 16; j++) {
        float x0 = vbuf[half*32 + 2*j    ][d];
        float x1 = vbuf[half*32 + 2*j + 1][d];
        __nv_bfloat16 ha, hb, la, lb;
        split1(x0, ha, la); split1(x1, hb, lb);
        hw[j] = pack2(ha, hb);
        lw[j] = pack2(la, lb);
    }
    size_t o = ((size_t)(b * HKV_ + kvh) * D_ + d) * S_ + s0 + half * 32;
    #pragma unroll
    for (int q = 0; q < 4; q++) {
        *(uint4*)(vhi + o + q * 8) = *(uint4*)&hw[q * 4];
        *(uint4*)(vlo + o + q * 8) = *(uint4*)&lw[q * 4];
    }
}

// ---------------------------------------------------------------------------
// Tensor-core flash attention. BLOCK_M=128 (8 warps x m16), BLOCK_N=64, D=128.
// Writes hi/lo bf16 splits of the output directly (consumed by out-proj GEMM).
// ---------------------------------------------------------------------------
#define A2_QBYTES 65536
#define A2_STAGE  65536
#define A2_SMEM   (A2_QBYTES + 2 * A2_STAGE)  // 196608

__global__ __launch_bounds__(256, 1)
void attn2(const __nv_bfloat16* __restrict__ qhi, const __nv_bfloat16* __restrict__ qlo,
           const __nv_bfloat16* __restrict__ khi, const __nv_bfloat16* __restrict__ klo,
           const __nv_bfloat16* __restrict__ vhi, const __nv_bfloat16* __restrict__ vlo,
           __nv_bfloat16* __restrict__ aohi, __nv_bfloat16* __restrict__ aolo)
{
    extern __shared__ char sm2[];
    uint32_t sb = s2u(sm2);
    int qt = blockIdx.x, h = blockIdx.y, b = blockIdx.z;
    int kvh = h / NGROUPS_;
    int q0 = qt * 128;
    int tid = threadIdx.x, wid = tid >> 5, lane = tid & 31;
    int lrow = lane & 15, lsel = lane >> 4;

    const char* qh_base = (const char*)(qhi + ((size_t)(b * H_ + h) * S_ + q0) * D_);
    const char* ql_base = (const char*)(qlo + ((size_t)(b * H_ + h) * S_ + q0) * D_);
    const char* kh_base = (const char*)(khi + ((size_t)(b * HKV_ + kvh) * S_) * D_);
    const char* kl_base = (const char*)(klo + ((size_t)(b * HKV_ + kvh) * S_) * D_);
    const char* vh_base = (const char*)(vhi + ((size_t)(b * HKV_ + kvh) * D_) * S_);
    const char* vl_base = (const char*)(vlo + ((size_t)(b * HKV_ + kvh) * D_) * S_);

    #pragma unroll
    for (int it = 0; it < 8; it++) {
        int idx = tid + it * 256;
        int r = idx >> 4, c = idx & 15;
        CP_ASYNC16(sb + swzq(r, c),          qh_base + r * 256 + c * 16);
        CP_ASYNC16(sb + 32768 + swzq(r, c),  ql_base + r * 256 + c * 16);
    }

    const int nt = 2 * qt + 2;

    auto load_kv = [&](int t, int st_i) {
        uint32_t st = sb + A2_QBYTES + (uint32_t)st_i * A2_STAGE;
        int k0 = t * 64;
        #pragma unroll
        for (int it = 0; it < 4; it++) {
            int idx = tid + it * 256;
            int r = idx >> 4, c = idx & 15;
            CP_ASYNC16(st + swzq(r, c),          kh_base + (size_t)(k0 + r) * 256 + c * 16);
            CP_ASYNC16(st + 16384 + swzq(r, c),  kl_base + (size_t)(k0 + r) * 256 + c * 16);
        }
        #pragma unroll
        for (int it = 0; it < 4; it++) {
            int idx = tid + it * 256;
            int r = idx >> 3, c = idx & 7;
            CP_ASYNC16(st + 32768 + swzv(r, c),
                       vh_base + (size_t)r * (S_ * 2) + k0 * 2 + c * 16);
            CP_ASYNC16(st + 49152 + swzv(r, c),
                       vl_base + (size_t)r * (S_ * 2) + k0 * 2 + c * 16);
        }
    };

    load_kv(0, 0);
    CP_COMMIT();

    float oacc[16][4];
    #pragma unroll
    for (int i = 0; i < 16; i++)
        #pragma unroll
        for (int j = 0; j < 4; j++) oacc[i][j] = 0.f;
    float m0 = -1e30f, m1 = -1e30f, l0 = 0.f, l1 = 0.f;

    for (int t = 0; t < nt; t++) {
        uint32_t st = sb + A2_QBYTES + (uint32_t)(t & 1) * A2_STAGE;
        if (t + 1 < nt) {
            load_kv(t + 1, (t + 1) & 1);
            CP_COMMIT();
            CP_WAIT1();
        } else {
            CP_WAIT0();
        }
        __syncthreads();

        float sacc[8][4];
        #pragma unroll
        for (int i = 0; i < 8; i++)
            #pragma unroll
            for (int j = 0; j < 4; j++) sacc[i][j] = 0.f;

        #pragma unroll
        for (int kc = 0; kc < 8; kc++) {
            uint32_t qa[4], qla[4];
            LDSM4(qa[0], qa[1], qa[2], qa[3],
                  sb + swzq(wid * 16 + lrow, kc * 2 + lsel));
            LDSM4(qla[0], qla[1], qla[2], qla[3],
                  sb + 32768 + swzq(wid * 16 + lrow, kc * 2 + lsel));
            uint32_t bh[8][2], bl[8][2];
            #pragma unroll
            for (int g = 0; g < 4; g++) {
                uint32_t r0, r1, r2, r3;
                LDSM4(r0, r1, r2, r3, st + swzq(g * 16 + lrow, kc * 2 + lsel));
                bh[2*g][0] = r0; bh[2*g][1] = r2;
                bh[2*g+1][0] = r1; bh[2*g+1][1] = r3;
                LDSM4(r0, r1, r2, r3, st + 16384 + swzq(g * 16 + lrow, kc * 2 + lsel));
                bl[2*g][0] = r0; bl[2*g][1] = r2;
                bl[2*g+1][0] = r1; bl[2*g+1][1] = r3;
            }
            #pragma unroll
            for (int nj = 0; nj < 8; nj++) {
                MMA16816(sacc[nj], qa, bh[nj]);
                MMA16816(sacc[nj], qa, bl[nj]);
                MMA16816(sacc[nj], qla, bh[nj]);
            }
        }

        int k0 = t * 64;
        if (t >= nt - 2) {
            int qr0 = q0 + wid * 16 + (lane >> 2);
            int qr1 = qr0 + 8;
            #pragma unroll
            for (int nj = 0; nj < 8; nj++) {
                int kcol = k0 + nj * 8 + (lane & 3) * 2;
                if (kcol     > qr0) sacc[nj][0] = -1e30f;
                if (kcol + 1 > qr0) sacc[nj][1] = -1e30f;
                if (kcol     > qr1) sacc[nj][2] = -1e30f;
                if (kcol + 1 > qr1) sacc[nj][3] = -1e30f;
            }
        }

        float mx0 = -1e30f, mx1 = -1e30f;
        #pragma unroll
        for (int nj = 0; nj < 8; nj++) {
            mx0 = fmaxf(mx0, fmaxf(sacc[nj][0], sacc[nj][1]));
            mx1 = fmaxf(mx1, fmaxf(sacc[nj][2], sacc[nj][3]));
        }
        mx0 = fmaxf(mx0, __shfl_xor_sync(0xffffffffu, mx0, 1));
        mx0 = fmaxf(mx0, __shfl_xor_sync(0xffffffffu, mx0, 2));
        mx1 = fmaxf(mx1, __shfl_xor_sync(0xffffffffu, mx1, 1));
        mx1 = fmaxf(mx1, __shfl_xor_sync(0xffffffffu, mx1, 2));
        float nm0 = fmaxf(m0, mx0), nm1 = fmaxf(m1, mx1);
        float f0 = ex2f(m0 - nm0), f1 = ex2f(m1 - nm1);
        m0 = nm0; m1 = nm1;

        uint32_t ph[4][4], pl[4][4];
        float rs0 = 0.f, rs1 = 0.f;
        #pragma unroll
        for (int j = 0; j < 4; j++) {
            float pe0 = ex2f(sacc[2*j][0] - nm0);
            float pe1 = ex2f(sacc[2*j][1] - nm0);
            float pe2 = ex2f(sacc[2*j][2] - nm1);
            float pe3 = ex2f(sacc[2*j][3] - nm1);
            float po0 = ex2f(sacc[2*j+1][0] - nm0);
            float po1 = ex2f(sacc[2*j+1][1] - nm0);
            float po2 = ex2f(sacc[2*j+1][2] - nm1);
            float po3 = ex2f(sacc[2*j+1][3] - nm1);
            rs0 += pe0 + pe1 + po0 + po1;
            rs1 += pe2 + pe3 + po2 + po3;
            ph[j][0] = packbf(pe0, pe1);
            ph[j][1] = packbf(pe2, pe3);
            ph[j][2] = packbf(po0, po1);
            ph[j][3] = packbf(po2, po3);
            __nv_bfloat16 hh; float r, q0r;
            hh = __float2bfloat16(pe0); q0r = pe0 - __bfloat162float(hh);
            hh = __float2bfloat16(pe1); r = pe1 - __bfloat162float(hh);
            pl[j][0] = packbf(q0r, r);
            hh = __float2bfloat16(pe2); q0r = pe2 - __bfloat162float(hh);
            hh = __float2bfloat16(pe3); r = pe3 - __bfloat162float(hh);
            pl[j][1] = packbf(q0r, r);
            hh = __float2bfloat16(po0); q0r = po0 - __bfloat162float(hh);
            hh = __float2bfloat16(po1); r = po1 - __bfloat162float(hh);
            pl[j][2] = packbf(q0r, r);
            hh = __float2bfloat16(po2); q0r = po2 - __bfloat162float(hh);
            hh = __float2bfloat16(po3); r = po3 - __bfloat162float(hh);
            pl[j][3] = packbf(q0r, r);
        }
        rs0 += __shfl_xor_sync(0xffffffffu, rs0, 1);
        rs0 += __shfl_xor_sync(0xffffffffu, rs0, 2);
        rs1 += __shfl_xor_sync(0xffffffffu, rs1, 1);
        rs1 += __shfl_xor_sync(0xffffffffu, rs1, 2);
        l0 = l0 * f0 + rs0;
        l1 = l1 * f1 + rs1;
        #pragma unroll
        for (int nj = 0; nj < 16; nj++) {
            oacc[nj][0] *= f0; oacc[nj][1] *= f0;
            oacc[nj][2] *= f1; oacc[nj][3] *= f1;
        }

        #pragma unroll
        for (int j = 0; j < 4; j++) {
            #pragma unroll
            for (int g = 0; g < 8; g++) {
                uint32_t r0, r1, r2, r3, s0r, s1r, s2r, s3r;
                LDSM4(r0, r1, r2, r3, st + 32768 + swzv(g * 16 + lrow, j * 2 + lsel));
                LDSM4(s0r, s1r, s2r, s3r, st + 49152 + swzv(g * 16 + lrow, j * 2 + lsel));
                uint32_t vh0[2] = {r0, r2}, vh1[2] = {r1, r3};
                uint32_t vl0[2] = {s0r, s2r}, vl1[2] = {s1r, s3r};
                MMA16816(oacc[2*g],   ph[j], vh0);
                MMA16816(oacc[2*g],   ph[j], vl0);
                MMA16816(oacc[2*g],   pl[j], vh0);
                MMA16816(oacc[2*g+1], ph[j], vh1);
                MMA16816(oacc[2*g+1], ph[j], vl1);
                MMA16816(oacc[2*g+1], pl[j], vh1);
            }
        }
        __syncthreads();
    }

    // ---- epilogue: write hi/lo bf16 splits directly ----
    float inv0 = 1.f / l0, inv1 = 1.f / l1;
    int r0g = q0 + wid * 16 + (lane >> 2);
    #pragma unroll
    for (int nj = 0; nj < 16; nj++) {
        int d = nj * 8 + (lane & 3) * 2;
        float a0 = oacc[nj][0] * inv0, a1 = oacc[nj][1] * inv0;
        float b0 = oacc[nj][2] * inv1, b1 = oacc[nj][3] * inv1;
        __nv_bfloat16 h0, h1, l0b, l1b;
        split1(a0, h0, l0b); split1(a1, h1, l1b);
        size_t off0 = ((size_t)(b * S_ + r0g)) * HID_ + h * D_ + d;
        *(uint32_t*)(aohi + off0) = pack2(h0, h1);
        *(uint32_t*)(aolo + off0) = pack2(l0b, l1b);
        split1(b0, h0, l0b); split1(b1, h1, l1b);
        size_t off1 = ((size_t)(b * S_ + r0g + 8)) * HID_ + h * D_ + d;
        *(uint32_t*)(aohi + off1) = pack2(h0, h1);
        *(uint32_t*)(aolo + off1) = pack2(l0b, l1b);
    }
}

// ---------------------------------------------------------------------------
extern "C" void kernel_launch(void* const* d_in, const int* in_sizes, int n_in,
                              void* d_out, int out_size)
{
    const float* x     = (const float*)d_in[0];
    const float* cosp  = (const float*)d_in[1];
    const float* sinp  = (const float*)d_in[2];
    const float* kci   = (const float*)d_in[3];
    const float* vci   = (const float*)d_in[4];
    const int*   slot  = (const int*)  d_in[5];
    const float* Wqkv  = (const float*)d_in[6];
    const float* bqkv  = (const float*)d_in[7];
    const float* Wo    = (const float*)d_in[8];

    float* out = (float*)d_out;
    float* kc  = out + (size_t)NTOK * HID_;
    float* vc  = kc  + (size_t)NSLOTS_ * HKV_ * D_;

    float* qkv; cudaGetSymbolAddress((void**)&qkv, g_qkv);
    __nv_bfloat16 *xhi, *xlo, *wqhi, *wqlo, *wohi, *wolo, *aohi, *aolo;
    __nv_bfloat16 *qhi, *qlo, *khi, *klo, *vhi, *vlo;
    cudaGetSymbolAddress((void**)&xhi,  g_xhi);
    cudaGetSymbolAddress((void**)&xlo,  g_xlo);
    cudaGetSymbolAddress((void**)&wqhi, g_wqhi);
    cudaGetSymbolAddress((void**)&wqlo, g_wqlo);
    cudaGetSymbolAddress((void**)&wohi, g_wohi);
    cudaGetSymbolAddress((void**)&wolo, g_wolo);
    cudaGetSymbolAddress((void**)&aohi, g_aohi);
    cudaGetSymbolAddress((void**)&aolo, g_aolo);
    cudaGetSymbolAddress((void**)&qhi,  g_qhi);
    cudaGetSymbolAddress((void**)&qlo,  g_qlo);
    cudaGetSymbolAddress((void**)&khi,  g_khi);
    cudaGetSymbolAddress((void**)&klo,  g_klo);
    cudaGetSymbolAddress((void**)&vhi,  g_vhi);
    cudaGetSymbolAddress((void**)&vlo,  g_vlo);

    cudaFuncSetAttribute(gemm_mma, cudaFuncAttributeMaxDynamicSharedMemorySize, MT_SMEM);
    cudaFuncSetAttribute(attn2, cudaFuncAttributeMaxDynamicSharedMemorySize, A2_SMEM);

    // 0) fp32 -> bf16 hi/lo splits for GEMM operands
    {
        int n4 = NTOK * HID_ / 4;
        split_bf16<<<(n4 + 255) / 256, 256>>>((const float4*)x, (uint2*)xhi, (uint2*)xlo, n4);
        n4 = QKV_N * HID_ / 4;
        split_bf16<<<(n4 + 255) / 256, 256>>>((const float4*)Wqkv, (uint2*)wqhi, (uint2*)wqlo, n4);
        n4 = HID_ * HID_ / 4;
        split_bf16<<<(n4 + 255) / 256, 256>>>((const float4*)Wo, (uint2*)wohi, (uint2*)wolo, n4);
    }

    // 1) QKV projection (tensor cores, 3-stage pipeline)
    gemm_mma<<<dim3(QKV_N / 128, NTOK / 128), 256, MT_SMEM>>>(
        xhi, xlo, wqhi, wqlo, bqkv, qkv, NTOK, QKV_N, HID_);

    // 2) Copy input caches to output (kvrope overwrites mapped slots after)
    {
        int n4 = NSLOTS_ * HKV_ * D_ / 4;
        copy_cache<<<(n4 + 255) / 256, 256>>>((const float4*)kci, (const float4*)vci,
                                              (float4*)kc, (float4*)vc, n4);
    }

    // 3) Fused RoPE + split + scatter (qkv read once, never written)
    {
        int n = NTOK * H_ * 16;
        qrope<<<(n + 255) / 256, 256>>>(qkv, cosp, sinp, qhi, qlo);
        kvrope<<<B_ * HKV_ * (S_ / 64), 256>>>(qkv, cosp, sinp, slot,
                                               kc, vc, khi, klo, vhi, vlo);
    }

    // 4) Tensor-core flash attention (writes hi/lo output splits directly)
    attn2<<<dim3(S_ / 128, H_, B_), 256, A2_SMEM>>>(qhi, qlo, khi, klo, vhi, vlo,
                                                    aohi, aolo);

    // 5) Output projection (tensor cores)
    gemm_mma<<<dim3(HID_ / 128, NTOK / 128), 256, MT_SMEM>>>(
        aohi, aolo, wohi, wolo, nullptr, out, NTOK, HID_, HID_);
}